// round 2
// baseline (speedup 1.0000x reference)
#include <cuda_runtime.h>
#include <math.h>

#define PI_D 3.141592653589793238462643383279502884

// ---------------- constant-ish device storage (no allocation) ----------------
__device__ float  W_S2_d[60 * 100];     // quadrature * wigner d_{m,0}(beta_in)
__device__ float  D_d[20 * 1330];       // per beta_out k: packed (l,u,v) wigner * (2l+1)
__device__ float2 KFT_d[100 * 6];       // kernel FT basis
__device__ float2 E60_d[19 * 60];       // e^{-2pi i a m / 60}, m=-9..9
__device__ float2 E20_d[20 * 19];       // e^{+2pi i p u / 20}, u=-9..9
__device__ double WQ_d[60];             // Driscoll-Healy quadrature weights
__device__ float2 FHAT_d[512 * 2 * 100];
__device__ float2 YC_d[5 * 2 * 100];    // conj(yhat)*SCALING, [o][i][s]

__constant__ int OFFL_c[11] = {0, 1, 10, 35, 84, 165, 286, 455, 680, 969, 1330};

// ---------------- Wigner-d (double, direct factorial formula) ----------------
__device__ double wig_d(int l, int mp, int m, double cb, double sb, const double* fact) {
    double cbp[20], sbp[20];
    cbp[0] = 1.0; sbp[0] = 1.0;
    for (int j = 1; j <= 2 * l; j++) { cbp[j] = cbp[j - 1] * cb; sbp[j] = sbp[j - 1] * sb; }
    double pref = sqrt(fact[l + m] * fact[l - m] * fact[l + mp] * fact[l - mp]);
    int smin = max(0, m - mp), smax = min(l + m, l - mp);
    double tot = 0.0;
    for (int s = smin; s <= smax; s++) {
        double den = fact[l + m - s] * fact[s] * fact[mp - m + s] * fact[l - mp - s];
        double t = cbp[2 * l + m - mp - 2 * s] * sbp[mp - m + 2 * s] / den;
        tot += ((mp - m + s) & 1) ? -t : t;
    }
    return pref * tot;
}

// ---------------- setup: quadrature weights ----------------
__global__ void k_setup_w() {
    int j = threadIdx.x;
    if (j >= 60) return;
    double beta = PI_D * (2 * j + 1) / 120.0;
    double s = 0.0;
    for (int k = 0; k < 30; k++)
        s += sin((double)(2 * j + 1) * (2 * k + 1) * PI_D / 120.0) / (double)(2 * k + 1);
    WQ_d[j] = (2.0 / 30.0) * sin(beta) * s;
}

// ---------------- setup: all tables ----------------
__global__ void k_setup_main() {
    int tid = blockIdx.x * blockDim.x + threadIdx.x;
    if (tid >= 34720) return;
    double fact[19];
    fact[0] = 1.0;
    for (int j = 1; j < 19; j++) fact[j] = fact[j - 1] * (double)j;

    if (tid < 26600) {
        // D_SO3: per beta_out k, packed (l, u, v)
        int k = tid / 1330, r = tid % 1330;
        int l = 0; while (OFFL_c[l + 1] <= r) l++;
        int j = r - OFFL_c[l]; int L = 2 * l + 1;
        int u = j / L - l, v = j % L - l;
        double beta = PI_D * (2 * k + 1) / 40.0;
        double cb = cos(beta * 0.5), sb = sin(beta * 0.5);
        D_d[tid] = (float)(wig_d(l, u, v, cb, sb, fact) * (double)(2 * l + 1));
    } else if (tid < 32600) {
        // W_S2[k][s] = w[k] * d^l_{m,0}(beta_in_k)
        int q = tid - 26600; int k = q / 100, s = q % 100;
        int l = 0; while ((l + 1) * (l + 1) <= s) l++;
        int m = s - l * l - l;
        double beta = PI_D * (2 * k + 1) / 120.0;
        double cb = cos(beta * 0.5), sb = sin(beta * 0.5);
        W_S2_d[k * 100 + s] = (float)(WQ_d[k] * wig_d(l, m, 0, cb, sb, fact));
    } else if (tid < 33200) {
        // K_FT[s][g] = d^l_{m,0}(pi/160) * e^{-i m * 2 pi g / 6}
        int q = tid - 32600; int s = q / 6, g = q % 6;
        int l = 0; while ((l + 1) * (l + 1) <= s) l++;
        int m = s - l * l - l;
        double beta = PI_D / 160.0;
        double cb = cos(beta * 0.5), sb = sin(beta * 0.5);
        double d0 = wig_d(l, m, 0, cb, sb, fact);
        double ga = 2.0 * PI_D * (double)g / 6.0;
        KFT_d[s * 6 + g] = make_float2((float)(d0 * cos((double)m * ga)),
                                       (float)(-d0 * sin((double)m * ga)));
    } else if (tid < 34340) {
        // E60[m+9][a] = e^{-2 pi i a m / 60}
        int q = tid - 33200; int mi = q / 60, a = q % 60;
        int m = mi - 9;
        double th = -2.0 * PI_D * (double)a * (double)m / 60.0;
        E60_d[mi * 60 + a] = make_float2((float)cos(th), (float)sin(th));
    } else {
        // E20[p][u+9] = e^{+2 pi i p u / 20}
        int q = tid - 34340; int p = q / 19, ui = q % 19;
        int u = ui - 9;
        double th = 2.0 * PI_D * (double)p * (double)u / 20.0;
        E20_d[p * 19 + ui] = make_float2((float)cos(th), (float)sin(th));
    }
}

// ---------------- stage 1: fhat[b][i][s] ----------------
__global__ __launch_bounds__(128) void k_fhat(const float* __restrict__ x) {
    __shared__ float  xs[3600];
    __shared__ float2 xf[60 * 19];
    __shared__ float2 e60[19 * 60];
    int bi = blockIdx.x;   // b*2 + i
    const float* xp = x + (size_t)bi * 3600;
    for (int t = threadIdx.x; t < 3600; t += 128) xs[t] = xp[t];
    for (int t = threadIdx.x; t < 19 * 60; t += 128) e60[t] = E60_d[t];
    __syncthreads();
    // 19-frequency DFT along alpha for each of 60 beta rows
    for (int t = threadIdx.x; t < 1140; t += 128) {
        int k = t / 19, mi = t % 19;
        float re = 0.f, im = 0.f;
        const float*  xr = xs + k * 60;
        const float2* er = e60 + mi * 60;
        #pragma unroll 4
        for (int a = 0; a < 60; a++) {
            float xv = xr[a]; float2 e = er[a];
            re += xv * e.x; im += xv * e.y;
        }
        xf[k * 19 + mi] = make_float2(re, im);
    }
    __syncthreads();
    // contract with quadrature-weighted wigner over beta
    for (int s = threadIdx.x; s < 100; s += 128) {
        int l = 0; while ((l + 1) * (l + 1) <= s) l++;
        int m = s - l * l - l;
        float re = 0.f, im = 0.f;
        #pragma unroll 4
        for (int k = 0; k < 60; k++) {
            float w = W_S2_d[k * 100 + s];
            float2 v = xf[k * 19 + (m + 9)];
            re += w * v.x; im += w * v.y;
        }
        FHAT_d[bi * 100 + s] = make_float2(re, im);
    }
}

// ---------------- stage 2: conj(yhat)*SCALING ----------------
__global__ void k_yhat(const float* __restrict__ kern) {
    __shared__ float ks[60];
    if (threadIdx.x < 60) ks[threadIdx.x] = kern[threadIdx.x];
    __syncthreads();
    float SC = (float)(1.0 / sqrt(6.0 * 2.0 * 10000.0 / 900.0));
    for (int tt = threadIdx.x; tt < 1000; tt += blockDim.x) {
        int s = tt % 100; int io = tt / 100; int i = io % 2; int o = io / 2;
        float re = 0.f, im = 0.f;
        #pragma unroll
        for (int g = 0; g < 6; g++) {
            float kv = ks[(i * 5 + o) * 6 + g];
            float2 kf = KFT_d[s * 6 + g];
            re += kv * kf.x; im += kv * kf.y;
        }
        YC_d[(o * 2 + i) * 100 + s] = make_float2(re * SC, -im * SC);
    }
}

// ---------------- stage 3: main — z, S_k, separable inverse transform ----------------
__global__ __launch_bounds__(256) void k_main(const float* __restrict__ bias,
                                              float* __restrict__ out) {
    __shared__ float2 Fs[200];
    __shared__ float2 Ys[200];
    __shared__ float2 zs[1330];
    __shared__ float2 e20[380];
    __shared__ float2 Sk[361];
    __shared__ float2 G[380];
    int b = blockIdx.x, o = blockIdx.y;
    int tid = threadIdx.x;
    for (int t = tid; t < 200; t += 256) Fs[t] = FHAT_d[b * 200 + t];
    for (int t = tid; t < 200; t += 256) Ys[t] = YC_d[o * 200 + t];
    for (int t = tid; t < 380; t += 256) e20[t] = E20_d[t];
    __syncthreads();
    // z_l[u,v] = sum_i fhat_l[u,i] * conj(yhat_l[v,i])
    for (int t = tid; t < 1330; t += 256) {
        int l = 0; while (OFFL_c[l + 1] <= t) l++;
        int j = t - OFFL_c[l]; int L = 2 * l + 1;
        int ui = j / L, vi = j % L;
        int su = l * l + ui, sv = l * l + vi;
        float2 f0 = Fs[su], f1 = Fs[100 + su], y0 = Ys[sv], y1 = Ys[100 + sv];
        float re = f0.x * y0.x - f0.y * y0.y + f1.x * y1.x - f1.y * y1.y;
        float im = f0.x * y0.y + f0.y * y0.x + f1.x * y1.y + f1.y * y1.x;
        zs[t] = make_float2(re, im);
    }
    __syncthreads();
    float bo = bias[o];
    float* outp = out + ((size_t)(b * 5 + o)) * 8000;
    for (int k = 0; k < 20; k++) {
        const float* Dk = D_d + k * 1330;
        // S_k[u,v] = sum_l D_l[k,u,v] * z_l[u,v]
        for (int t = tid; t < 361; t += 256) {
            int ui = t / 19, vi = t % 19;
            int u = ui - 9, v = vi - 9;
            int au = abs(u), av = abs(v);
            int lmin = max(au, av);
            float re = 0.f, im = 0.f;
            for (int l = lmin; l < 10; l++) {
                int idx = OFFL_c[l] + (u + l) * (2 * l + 1) + (v + l);
                float d = Dk[idx];
                float2 zv = zs[idx];
                re += d * zv.x; im += d * zv.y;
            }
            Sk[t] = make_float2(re, im);
        }
        __syncthreads();
        // G[u,q] = sum_v S_k[u,v] * e^{+2 pi i q v / 20}
        for (int t = tid; t < 380; t += 256) {
            int ui = t / 20, q = t % 20;
            float re = 0.f, im = 0.f;
            const float2* Sr = Sk + ui * 19;
            const float2* Er = e20 + q * 19;
            #pragma unroll
            for (int vi = 0; vi < 19; vi++) {
                float2 s = Sr[vi], e = Er[vi];
                re += s.x * e.x - s.y * e.y;
                im += s.x * e.y + s.y * e.x;
            }
            G[ui * 20 + q] = make_float2(re, im);
        }
        __syncthreads();
        // out[p,q] = Re( sum_u e^{+2 pi i p u / 20} * G[u,q] ) + bias
        for (int t = tid; t < 400; t += 256) {
            int p = t / 20, q = t % 20;
            float acc = bo;
            const float2* Er = e20 + p * 19;
            #pragma unroll
            for (int ui = 0; ui < 19; ui++) {
                float2 e = Er[ui]; float2 g = G[ui * 20 + q];
                acc += e.x * g.x - e.y * g.y;
            }
            outp[k * 400 + t] = acc;
        }
        __syncthreads();
    }
}

// ---------------- launch ----------------
extern "C" void kernel_launch(void* const* d_in, const int* in_sizes, int n_in,
                              void* d_out, int out_size) {
    const float* x    = (const float*)d_in[0];  // (512, 2, 60, 60)
    const float* kern = (const float*)d_in[1];  // (2, 5, 6)
    const float* bias = (const float*)d_in[2];  // (5)
    float* out = (float*)d_out;                 // (512, 5, 20, 20, 20)

    k_setup_w<<<1, 64>>>();
    k_setup_main<<<136, 256>>>();
    k_fhat<<<1024, 128>>>(x);
    k_yhat<<<1, 256>>>(kern);
    dim3 g(512, 5);
    k_main<<<g, 256>>>(bias, out);
}

// round 3
// speedup vs baseline: 1.6163x; 1.6163x over previous
#include <cuda_runtime.h>
#include <math.h>

#define PI_D 3.141592653589793238462643383279502884

// ---------------- device storage (no allocation) ----------------
__device__ float  W_S2p_d[60 * 55];     // quadrature * wigner d_{m,0}, m>=0 packed
__device__ float  D_d[20 * 715];        // per beta_out k: packed (l, u>=0, v) wigner * (2l+1)
__device__ float2 KFT_d[100 * 6];       // kernel FT basis (full spectrum)
__device__ float2 E60T_d[60 * 10];      // [a][m] e^{-2pi i a m / 60}, m=0..9
__device__ float2 E20T_d[19 * 20];      // [vi][q] e^{+2pi i q (vi-9) / 20}
__device__ float2 E20P_d[20 * 9];       // [p][u-1] 2*e^{+2pi i p u / 20}, u=1..9
__device__ double WQ_d[60];             // Driscoll-Healy quadrature weights
__device__ float2 FHAT_d[512 * 2 * 100];
__device__ float2 YC_d[5 * 2 * 100];    // conj(yhat)*SCALING, [o][i][s]

// OFFU[l] = sum_{j<l} (j+1)(2j+1)  (u>=0 packed layout)
__constant__ int OFFU_c[11] = {0, 1, 7, 22, 50, 95, 161, 252, 372, 525, 715};

// ---------------- Wigner-d (double, factorial formula, no division) ----------------
__device__ double wig_d(int l, int mp, int m, double cb, double sb,
                        const double* fact, const double* ifact) {
    double cbp[20], sbp[20];
    cbp[0] = 1.0; sbp[0] = 1.0;
    for (int j = 1; j <= 2 * l; j++) { cbp[j] = cbp[j - 1] * cb; sbp[j] = sbp[j - 1] * sb; }
    double pref = sqrt(fact[l + m] * fact[l - m] * fact[l + mp] * fact[l - mp]);
    int smin = max(0, m - mp), smax = min(l + m, l - mp);
    double tot = 0.0;
    for (int s = smin; s <= smax; s++) {
        double inv = ifact[l + m - s] * ifact[s] * ifact[mp - m + s] * ifact[l - mp - s];
        double t = cbp[2 * l + m - mp - 2 * s] * sbp[mp - m + 2 * s] * inv;
        tot += ((mp - m + s) & 1) ? -t : t;
    }
    return pref * tot;
}

// ---------------- setup: quadrature weights ----------------
__global__ void k_setup_w() {
    int j = threadIdx.x;
    if (j >= 60) return;
    double beta = PI_D * (2 * j + 1) / 120.0;
    double s = 0.0;
    for (int k = 0; k < 30; k++)
        s += sin((double)(2 * j + 1) * (2 * k + 1) * PI_D / 120.0) / (double)(2 * k + 1);
    WQ_d[j] = (2.0 / 30.0) * sin(beta) * s;
}

// ---------------- setup: all tables ----------------
__global__ void k_setup_main() {
    int tid = blockIdx.x * blockDim.x + threadIdx.x;
    if (tid >= 19360) return;
    double fact[19], ifact[19];
    fact[0] = 1.0;
    for (int j = 1; j < 19; j++) fact[j] = fact[j - 1] * (double)j;
    ifact[18] = 1.0 / fact[18];
    for (int j = 18; j > 0; j--) ifact[j - 1] = ifact[j] * (double)j;

    if (tid < 14300) {
        // D packed: k in [0,20), r in [0,715): (l, u>=0, v)
        int k = tid / 715, r = tid % 715;
        int l = 0;
        #pragma unroll
        for (int j = 1; j < 10; j++) if (OFFU_c[j] <= r) l = j;
        int jj = r - OFFU_c[l]; int L = 2 * l + 1;
        int u = jj / L, v = jj % L - l;
        double beta = PI_D * (2 * k + 1) / 40.0;
        double cb = cos(beta * 0.5), sb = sin(beta * 0.5);
        D_d[tid] = (float)(wig_d(l, u, v, cb, sb, fact, ifact) * (double)(2 * l + 1));
    } else if (tid < 17600) {
        // W_S2 packed m>=0: [k][sp], sp = l(l+1)/2 + m
        int q = tid - 14300; int k = q / 55, sp = q % 55;
        int l = 0;
        #pragma unroll
        for (int j = 1; j < 10; j++) if (j * (j + 1) / 2 <= sp) l = j;
        int m = sp - l * (l + 1) / 2;
        double beta = PI_D * (2 * k + 1) / 120.0;
        double cb = cos(beta * 0.5), sb = sin(beta * 0.5);
        W_S2p_d[k * 55 + sp] = (float)(WQ_d[k] * wig_d(l, m, 0, cb, sb, fact, ifact));
    } else if (tid < 18200) {
        // K_FT[s][g] (full spectrum)
        int q = tid - 17600; int s = q / 6, g = q % 6;
        int l = 0;
        #pragma unroll
        for (int j = 1; j < 10; j++) if (j * j <= s) l = j;
        int m = s - l * l - l;
        double beta = PI_D / 160.0;
        double cb = cos(beta * 0.5), sb = sin(beta * 0.5);
        double d0 = wig_d(l, m, 0, cb, sb, fact, ifact);
        double ga = 2.0 * PI_D * (double)g / 6.0;
        KFT_d[s * 6 + g] = make_float2((float)(d0 * cos((double)m * ga)),
                                       (float)(-d0 * sin((double)m * ga)));
    } else if (tid < 18800) {
        // E60T[a][m] = e^{-2 pi i a m / 60}, m = 0..9
        int q = tid - 18200; int a = q / 10, mi = q % 10;
        double th = -2.0 * PI_D * (double)a * (double)mi / 60.0;
        E60T_d[a * 10 + mi] = make_float2((float)cos(th), (float)sin(th));
    } else if (tid < 19180) {
        // E20T[vi][q] = e^{+2 pi i q (vi-9) / 20}
        int q = tid - 18800; int vi = q / 20, qq = q % 20;
        double th = 2.0 * PI_D * (double)qq * (double)(vi - 9) / 20.0;
        E20T_d[vi * 20 + qq] = make_float2((float)cos(th), (float)sin(th));
    } else {
        // E20P[p][u-1] = 2 e^{+2 pi i p u / 20}, u = 1..9
        int q = tid - 19180; int p = q / 9, ui = q % 9;
        double th = 2.0 * PI_D * (double)p * (double)(ui + 1) / 20.0;
        E20P_d[p * 9 + ui] = make_float2((float)(2.0 * cos(th)), (float)(2.0 * sin(th)));
    }
}

// ---------------- stage 1: fhat[b][i][s] (real-input DFT, m=0..9 + mirror) ----------------
__global__ __launch_bounds__(128) void k_fhat(const float* __restrict__ x) {
    __shared__ float  xsT[60 * 61];   // [a][k], pitch 61 = conflict-free
    __shared__ float2 xf2[600];       // [k][m], m=0..9
    __shared__ float2 e60[600];       // [a][m]
    int bi = blockIdx.x;   // b*2 + i
    const float* xp = x + (size_t)bi * 3600;
    for (int t = threadIdx.x; t < 3600; t += 128) {
        int k = t / 60, a = t % 60;
        xsT[a * 61 + k] = xp[t];
    }
    for (int t = threadIdx.x; t < 600; t += 128) e60[t] = E60T_d[t];
    __syncthreads();
    // DFT along alpha: per (m, k). Lanes: consecutive k (coalesced xsT, broadcast e60).
    for (int t = threadIdx.x; t < 600; t += 128) {
        int mi = t / 60, k = t % 60;
        float re = 0.f, im = 0.f;
        #pragma unroll 4
        for (int a = 0; a < 60; a++) {
            float xv = xsT[a * 61 + k];
            float2 e = e60[a * 10 + mi];
            re += xv * e.x; im += xv * e.y;
        }
        xf2[k * 10 + mi] = make_float2(re, im);
    }
    __syncthreads();
    // contract over beta with packed weights; mirror negative m
    if (threadIdx.x < 55) {
        int t = threadIdx.x;
        int l = 0;
        #pragma unroll
        for (int j = 1; j < 10; j++) if (j * (j + 1) / 2 <= t) l = j;
        int m = t - l * (l + 1) / 2;
        float re = 0.f, im = 0.f;
        #pragma unroll 4
        for (int k = 0; k < 60; k++) {
            float w = W_S2p_d[k * 55 + t];
            float2 v = xf2[k * 10 + m];
            re += w * v.x; im += w * v.y;
        }
        FHAT_d[bi * 100 + l * l + l + m] = make_float2(re, im);
        if (m > 0) {
            float sg = (m & 1) ? -1.f : 1.f;
            FHAT_d[bi * 100 + l * l + l - m] = make_float2(sg * re, -sg * im);
        }
    }
}

// ---------------- stage 2: conj(yhat)*SCALING ----------------
__global__ void k_yhat(const float* __restrict__ kern) {
    __shared__ float ks[60];
    if (threadIdx.x < 60) ks[threadIdx.x] = kern[threadIdx.x];
    __syncthreads();
    float SC = (float)(1.0 / sqrt(6.0 * 2.0 * 10000.0 / 900.0));
    for (int tt = threadIdx.x; tt < 1000; tt += blockDim.x) {
        int s = tt % 100; int io = tt / 100; int i = io % 2; int o = io / 2;
        float re = 0.f, im = 0.f;
        #pragma unroll
        for (int g = 0; g < 6; g++) {
            float kv = ks[(i * 5 + o) * 6 + g];
            float2 kf = KFT_d[s * 6 + g];
            re += kv * kf.x; im += kv * kf.y;
        }
        YC_d[(o * 2 + i) * 100 + s] = make_float2(re * SC, -im * SC);
    }
}

// ---------------- stage 3: main — z(u>=0), S_k, symmetric separable inverse ----------------
__global__ __launch_bounds__(256) void k_main(const float* __restrict__ bias,
                                              float* __restrict__ out) {
    __shared__ float2 Fs[200];
    __shared__ float2 Ys[200];
    __shared__ float2 zs[715];     // packed u>=0
    __shared__ float2 e20t[380];   // [vi][q]
    __shared__ float2 e20p[180];   // [p][u-1], pre-doubled
    __shared__ float2 Sk[190];     // [u(0..9)][vi]
    __shared__ float2 G[200];      // [u(0..9)][q]
    int b = blockIdx.x, o = blockIdx.y;
    int tid = threadIdx.x;
    for (int t = tid; t < 200; t += 256) Fs[t] = FHAT_d[b * 200 + t];
    for (int t = tid; t < 200; t += 256) Ys[t] = YC_d[o * 200 + t];
    for (int t = tid; t < 380; t += 256) e20t[t] = E20T_d[t];
    for (int t = tid; t < 180; t += 256) e20p[t] = E20P_d[t];
    __syncthreads();
    // z_l[u,v] = sum_i fhat_l[u,i] * conj(yhat_l[v,i]), u >= 0 only
    for (int t = tid; t < 715; t += 256) {
        int l = 0;
        #pragma unroll
        for (int j = 1; j < 10; j++) if (OFFU_c[j] <= t) l = j;
        int jj = t - OFFU_c[l]; int L = 2 * l + 1;
        int u = jj / L, vi = jj % L;
        int su = l * l + l + u, sv = l * l + vi;
        float2 f0 = Fs[su], f1 = Fs[100 + su], y0 = Ys[sv], y1 = Ys[100 + sv];
        float re = f0.x * y0.x - f0.y * y0.y + f1.x * y1.x - f1.y * y1.y;
        float im = f0.x * y0.y + f0.y * y0.x + f1.x * y1.y + f1.y * y1.x;
        zs[t] = make_float2(re, im);
    }
    __syncthreads();
    float bo = bias[o];
    float* outp = out + ((size_t)(b * 5 + o)) * 8000;
    for (int k = 0; k < 20; k++) {
        const float* Dk = D_d + k * 715;
        // S_k[u,v] = sum_l D_l[k,u,v] * z_l[u,v], u >= 0
        if (tid < 190) {
            int u = tid / 19, vi = tid % 19;
            int v = vi - 9;
            int av = v < 0 ? -v : v;
            int lmin = u > av ? u : av;
            float re = 0.f, im = 0.f;
            for (int l = lmin; l < 10; l++) {
                int idx = OFFU_c[l] + u * (2 * l + 1) + v + l;
                float d = Dk[idx];
                float2 zv = zs[idx];
                re += d * zv.x; im += d * zv.y;
            }
            Sk[tid] = make_float2(re, im);
        }
        __syncthreads();
        // G[u,q] = sum_v S_k[u,v] * e^{+2 pi i q v / 20}, u >= 0
        if (tid < 200) {
            int u = tid / 20, q = tid % 20;
            float re = 0.f, im = 0.f;
            const float2* Sr = Sk + u * 19;
            #pragma unroll
            for (int vi = 0; vi < 19; vi++) {
                float2 s = Sr[vi];
                float2 e = e20t[vi * 20 + q];
                re += s.x * e.x - s.y * e.y;
                im += s.x * e.y + s.y * e.x;
            }
            G[u * 20 + q] = make_float2(re, im);
        }
        __syncthreads();
        // out[p,q] = bias + G[0,q].re + sum_{u=1..9} 2*Re(E[p,u]*G[u,q])
        for (int t = tid; t < 400; t += 256) {
            int p = t / 20, q = t % 20;
            float acc = bo + G[q].x;
            const float2* Ep = e20p + p * 9;
            #pragma unroll
            for (int uu = 0; uu < 9; uu++) {
                float2 e = Ep[uu];
                float2 g = G[(uu + 1) * 20 + q];
                acc += e.x * g.x - e.y * g.y;   // e pre-scaled by 2
            }
            outp[k * 400 + t] = acc;
        }
        __syncthreads();
    }
}

// ---------------- launch ----------------
extern "C" void kernel_launch(void* const* d_in, const int* in_sizes, int n_in,
                              void* d_out, int out_size) {
    const float* x    = (const float*)d_in[0];  // (512, 2, 60, 60)
    const float* kern = (const float*)d_in[1];  // (2, 5, 6)
    const float* bias = (const float*)d_in[2];  // (5)
    float* out = (float*)d_out;                 // (512, 5, 20, 20, 20)

    k_setup_w<<<1, 64>>>();
    k_setup_main<<<76, 256>>>();
    k_fhat<<<1024, 128>>>(x);
    k_yhat<<<1, 256>>>(kern);
    dim3 g(512, 5);
    k_main<<<g, 256>>>(bias, out);
}

// round 4
// speedup vs baseline: 1.8290x; 1.1316x over previous
#include <cuda_runtime.h>
#include <math.h>
#include <string.h>

#define PI_D 3.141592653589793238462643383279502884

// ---------------- packed table layout (floats) ----------------
// OFF_D    : D_SO3 packed (k,[l,u>=0,v]) * (2l+1)          : 20*715  = 14300
// OFF_W    : quadrature * wigner d_{m,0}(beta_in), m>=0    : 60*55   = 3300
// OFF_KFT  : kernel FT basis, float2 [s][g]                : 100*6*2 = 1200
// OFF_E60  : float2 [a][m] e^{-2pi i a m/60}, m=0..9       : 60*10*2 = 1200
// OFF_E20T : float2 [vi][q] e^{+2pi i q(vi-9)/20}          : 19*20*2 = 760
// OFF_E20P : float2 [p][u-1] 2 e^{+2pi i p u/20}, u=1..9   : 20*9*2  = 360
#define OFF_D    0
#define OFF_W    14300
#define OFF_KFT  17600
#define OFF_E60  18800
#define OFF_E20T 20000
#define OFF_E20P 20760
#define TAB_LEN  21120

__device__ __align__(16) float TAB_d[TAB_LEN];
__device__ float2 FHAT_d[512 * 2 * 100];
__device__ float2 YC_d[5 * 2 * 100];    // conj(yhat)*SCALING, [o][i][s]

// OFFU[l] = sum_{j<l} (j+1)(2j+1)  (u>=0 packed layout)
__constant__ int OFFU_c[11] = {0, 1, 7, 22, 50, 95, 161, 252, 372, 525, 715};
static const int OFFU_h[11] = {0, 1, 7, 22, 50, 95, 161, 252, 372, 525, 715};

// ================= HOST table generation (runs at capture time only) =========
static double h_fact[19];

static double h_wig(int l, int mp, int m, double cb, double sb) {
    double pref = sqrt(h_fact[l + m] * h_fact[l - m] * h_fact[l + mp] * h_fact[l - mp]);
    int smin = (m - mp) > 0 ? (m - mp) : 0;
    int smax = (l + m) < (l - mp) ? (l + m) : (l - mp);
    double tot = 0.0;
    for (int s = smin; s <= smax; s++) {
        double den = h_fact[l + m - s] * h_fact[s] * h_fact[mp - m + s] * h_fact[l - mp - s];
        double t = pow(cb, (double)(2 * l + m - mp - 2 * s)) * pow(sb, (double)(mp - m + 2 * s)) / den;
        tot += ((mp - m + s) & 1) ? -t : t;
    }
    return pref * tot;
}

static float host_tab[TAB_LEN];

static void h_build_tables() {
    h_fact[0] = 1.0;
    for (int j = 1; j < 19; j++) h_fact[j] = h_fact[j - 1] * (double)j;

    // quadrature weights (Driscoll-Healy, B_IN=30)
    double wq[60];
    for (int j = 0; j < 60; j++) {
        double beta = PI_D * (2 * j + 1) / 120.0;
        double s = 0.0;
        for (int k = 0; k < 30; k++)
            s += sin((double)(2 * j + 1) * (2 * k + 1) * PI_D / 120.0) / (double)(2 * k + 1);
        wq[j] = (2.0 / 30.0) * sin(beta) * s;
    }

    // D packed: k in [0,20), (l, u in [0,l], v in [-l,l]), * (2l+1)
    for (int k = 0; k < 20; k++) {
        double beta = PI_D * (2 * k + 1) / 40.0;
        double cb = cos(beta * 0.5), sb = sin(beta * 0.5);
        for (int l = 0; l < 10; l++) {
            int L = 2 * l + 1;
            for (int u = 0; u <= l; u++)
                for (int vi = 0; vi < L; vi++) {
                    int idx = OFFU_h[l] + u * L + vi;
                    host_tab[OFF_D + k * 715 + idx] =
                        (float)(h_wig(l, u, vi - l, cb, sb) * (double)L);
                }
        }
    }

    // W_S2 packed m>=0: [k][sp], sp = l(l+1)/2 + m ; value = wq[k]*d^l_{m,0}(beta_in_k)
    for (int k = 0; k < 60; k++) {
        double beta = PI_D * (2 * k + 1) / 120.0;
        double cb = cos(beta * 0.5), sb = sin(beta * 0.5);
        for (int l = 0; l < 10; l++)
            for (int m = 0; m <= l; m++)
                host_tab[OFF_W + k * 55 + l * (l + 1) / 2 + m] =
                    (float)(wq[k] * h_wig(l, m, 0, cb, sb));
    }

    // K_FT[s][g] = d^l_{m,0}(pi/160) * e^{-i m 2 pi g/6}   (full spectrum s = l^2 + l + m)
    {
        double beta = PI_D / 160.0;
        double cb = cos(beta * 0.5), sb = sin(beta * 0.5);
        for (int l = 0; l < 10; l++)
            for (int m = -l; m <= l; m++) {
                int s = l * l + l + m;
                double d0 = h_wig(l, m, 0, cb, sb);
                for (int g = 0; g < 6; g++) {
                    double ga = 2.0 * PI_D * (double)g / 6.0;
                    host_tab[OFF_KFT + (s * 6 + g) * 2 + 0] = (float)(d0 * cos((double)m * ga));
                    host_tab[OFF_KFT + (s * 6 + g) * 2 + 1] = (float)(-d0 * sin((double)m * ga));
                }
            }
    }

    // E60T[a][m] = e^{-2 pi i a m / 60}, m=0..9
    for (int a = 0; a < 60; a++)
        for (int m = 0; m < 10; m++) {
            double th = -2.0 * PI_D * (double)a * (double)m / 60.0;
            host_tab[OFF_E60 + (a * 10 + m) * 2 + 0] = (float)cos(th);
            host_tab[OFF_E60 + (a * 10 + m) * 2 + 1] = (float)sin(th);
        }

    // E20T[vi][q] = e^{+2 pi i q (vi-9)/20}
    for (int vi = 0; vi < 19; vi++)
        for (int q = 0; q < 20; q++) {
            double th = 2.0 * PI_D * (double)q * (double)(vi - 9) / 20.0;
            host_tab[OFF_E20T + (vi * 20 + q) * 2 + 0] = (float)cos(th);
            host_tab[OFF_E20T + (vi * 20 + q) * 2 + 1] = (float)sin(th);
        }

    // E20P[p][u-1] = 2 e^{+2 pi i p u/20}, u=1..9
    for (int p = 0; p < 20; p++)
        for (int u = 1; u <= 9; u++) {
            double th = 2.0 * PI_D * (double)p * (double)u / 20.0;
            host_tab[OFF_E20P + (p * 9 + u - 1) * 2 + 0] = (float)(2.0 * cos(th));
            host_tab[OFF_E20P + (p * 9 + u - 1) * 2 + 1] = (float)(2.0 * sin(th));
        }
}

// ================= stage 1: fhat[b][i][s] ====================================
__global__ __launch_bounds__(128) void k_fhat(const float* __restrict__ x) {
    __shared__ float  xsT[60 * 61];   // [a][k], pitch 61 = conflict-free
    __shared__ float2 xf2[600];       // [k][m], m=0..9
    __shared__ float2 e60[600];       // [a][m]
    int bi = blockIdx.x;   // b*2 + i
    const float* xp = x + (size_t)bi * 3600;
    const float2* E60g = (const float2*)(TAB_d + OFF_E60);
    for (int t = threadIdx.x; t < 3600; t += 128) {
        int k = t / 60, a = t % 60;
        xsT[a * 61 + k] = xp[t];
    }
    for (int t = threadIdx.x; t < 600; t += 128) e60[t] = E60g[t];
    __syncthreads();
    // DFT along alpha: per (m, k). Lanes: consecutive k (coalesced xsT, broadcast e60).
    for (int t = threadIdx.x; t < 600; t += 128) {
        int mi = t / 60, k = t % 60;
        float re = 0.f, im = 0.f;
        #pragma unroll 4
        for (int a = 0; a < 60; a++) {
            float xv = xsT[a * 61 + k];
            float2 e = e60[a * 10 + mi];
            re += xv * e.x; im += xv * e.y;
        }
        xf2[k * 10 + mi] = make_float2(re, im);
    }
    __syncthreads();
    // contract over beta with packed weights; mirror negative m
    if (threadIdx.x < 55) {
        int t = threadIdx.x;
        int l = 0;
        #pragma unroll
        for (int j = 1; j < 10; j++) if (j * (j + 1) / 2 <= t) l = j;
        int m = t - l * (l + 1) / 2;
        float re = 0.f, im = 0.f;
        #pragma unroll 4
        for (int k = 0; k < 60; k++) {
            float w = TAB_d[OFF_W + k * 55 + t];
            float2 v = xf2[k * 10 + m];
            re += w * v.x; im += w * v.y;
        }
        FHAT_d[bi * 100 + l * l + l + m] = make_float2(re, im);
        if (m > 0) {
            float sg = (m & 1) ? -1.f : 1.f;
            FHAT_d[bi * 100 + l * l + l - m] = make_float2(sg * re, -sg * im);
        }
    }
}

// ================= stage 2: conj(yhat)*SCALING ===============================
__global__ void k_yhat(const float* __restrict__ kern) {
    __shared__ float ks[60];
    if (threadIdx.x < 60) ks[threadIdx.x] = kern[threadIdx.x];
    __syncthreads();
    const float2* KFT = (const float2*)(TAB_d + OFF_KFT);
    float SC = (float)(1.0 / sqrt(6.0 * 2.0 * 10000.0 / 900.0));
    for (int tt = threadIdx.x; tt < 1000; tt += blockDim.x) {
        int s = tt % 100; int io = tt / 100; int i = io % 2; int o = io / 2;
        float re = 0.f, im = 0.f;
        #pragma unroll
        for (int g = 0; g < 6; g++) {
            float kv = ks[(i * 5 + o) * 6 + g];
            float2 kf = KFT[s * 6 + g];
            re += kv * kf.x; im += kv * kf.y;
        }
        YC_d[(o * 2 + i) * 100 + s] = make_float2(re * SC, -im * SC);
    }
}

// ================= stage 3: main — z(u>=0), S_k, symmetric separable inverse =
__global__ __launch_bounds__(256) void k_main(const float* __restrict__ bias,
                                              float* __restrict__ out) {
    __shared__ float2 Fs[200];
    __shared__ float2 Ys[200];
    __shared__ float2 zs[715];     // packed u>=0
    __shared__ float2 e20t[380];   // [vi][q]
    __shared__ float2 e20p[180];   // [p][u-1], pre-doubled
    __shared__ float2 Sk[190];     // [u(0..9)][vi]
    __shared__ float2 G[200];      // [u(0..9)][q]
    int b = blockIdx.x, o = blockIdx.y;
    int tid = threadIdx.x;
    const float2* E20Tg = (const float2*)(TAB_d + OFF_E20T);
    const float2* E20Pg = (const float2*)(TAB_d + OFF_E20P);
    for (int t = tid; t < 200; t += 256) Fs[t] = FHAT_d[b * 200 + t];
    for (int t = tid; t < 200; t += 256) Ys[t] = YC_d[o * 200 + t];
    for (int t = tid; t < 380; t += 256) e20t[t] = E20Tg[t];
    for (int t = tid; t < 180; t += 256) e20p[t] = E20Pg[t];
    __syncthreads();
    // z_l[u,v] = sum_i fhat_l[u,i] * conj(yhat_l[v,i]), u >= 0 only
    for (int t = tid; t < 715; t += 256) {
        int l = 0;
        #pragma unroll
        for (int j = 1; j < 10; j++) if (OFFU_c[j] <= t) l = j;
        int jj = t - OFFU_c[l]; int L = 2 * l + 1;
        int u = jj / L, vi = jj % L;
        int su = l * l + l + u, sv = l * l + vi;
        float2 f0 = Fs[su], f1 = Fs[100 + su], y0 = Ys[sv], y1 = Ys[100 + sv];
        float re = f0.x * y0.x - f0.y * y0.y + f1.x * y1.x - f1.y * y1.y;
        float im = f0.x * y0.y + f0.y * y0.x + f1.x * y1.y + f1.y * y1.x;
        zs[t] = make_float2(re, im);
    }
    __syncthreads();
    float bo = bias[o];
    float* outp = out + ((size_t)(b * 5 + o)) * 8000;
    for (int k = 0; k < 20; k++) {
        const float* Dk = TAB_d + OFF_D + k * 715;
        // S_k[u,v] = sum_l D_l[k,u,v] * z_l[u,v], u >= 0
        if (tid < 190) {
            int u = tid / 19, vi = tid % 19;
            int v = vi - 9;
            int av = v < 0 ? -v : v;
            int lmin = u > av ? u : av;
            float re = 0.f, im = 0.f;
            for (int l = lmin; l < 10; l++) {
                int idx = OFFU_c[l] + u * (2 * l + 1) + v + l;
                float d = Dk[idx];
                float2 zv = zs[idx];
                re += d * zv.x; im += d * zv.y;
            }
            Sk[tid] = make_float2(re, im);
        }
        __syncthreads();
        // G[u,q] = sum_v S_k[u,v] * e^{+2 pi i q v / 20}, u >= 0
        if (tid < 200) {
            int u = tid / 20, q = tid % 20;
            float re = 0.f, im = 0.f;
            const float2* Sr = Sk + u * 19;
            #pragma unroll
            for (int vi = 0; vi < 19; vi++) {
                float2 s = Sr[vi];
                float2 e = e20t[vi * 20 + q];
                re += s.x * e.x - s.y * e.y;
                im += s.x * e.y + s.y * e.x;
            }
            G[u * 20 + q] = make_float2(re, im);
        }
        __syncthreads();
        // out[p,q] = bias + G[0,q].re + sum_{u=1..9} 2*Re(E[p,u]*G[u,q])
        for (int t = tid; t < 400; t += 256) {
            int p = t / 20, q = t % 20;
            float acc = bo + G[q].x;
            const float2* Ep = e20p + p * 9;
            #pragma unroll
            for (int uu = 0; uu < 9; uu++) {
                float2 e = Ep[uu];
                float2 g = G[(uu + 1) * 20 + q];
                acc += e.x * g.x - e.y * g.y;   // e pre-scaled by 2
            }
            outp[k * 400 + t] = acc;
        }
        __syncthreads();
    }
}

// ================= launch ====================================================
extern "C" void kernel_launch(void* const* d_in, const int* in_sizes, int n_in,
                              void* d_out, int out_size) {
    const float* x    = (const float*)d_in[0];  // (512, 2, 60, 60)
    const float* kern = (const float*)d_in[1];  // (2, 5, 6)
    const float* bias = (const float*)d_in[2];  // (5)
    float* out = (float*)d_out;                 // (512, 5, 20, 20, 20)

    // Host-side table build (runs at capture time; graph replays only the copy)
    h_build_tables();
    cudaMemcpyToSymbolAsync(TAB_d, host_tab, sizeof(float) * TAB_LEN, 0,
                            cudaMemcpyHostToDevice, 0);

    k_fhat<<<1024, 128>>>(x);
    k_yhat<<<1, 256>>>(kern);
    dim3 g(512, 5);
    k_main<<<g, 256>>>(bias, out);
}

// round 5
// speedup vs baseline: 2.0712x; 1.1324x over previous
#include <cuda_runtime.h>
#include <math.h>
#include <string.h>

#define PI_D 3.141592653589793238462643383279502884

// ---------------- packed table layout (floats) ----------------
#define OFF_D    0
#define OFF_W    14300
#define OFF_KFT  17600
#define OFF_E60  18800
#define OFF_E20T 20000
#define OFF_E20P 20760
#define TAB_LEN  21120

__device__ __align__(16) float TAB_d[TAB_LEN];
__device__ float2 FHAT_d[512 * 2 * 100];
__device__ float2 YC_d[5 * 2 * 100];    // conj(yhat)*SCALING, [o][i][s]

// OFFU[l] = sum_{j<l} (j+1)(2j+1)  (u>=0 packed layout)
__constant__ int OFFU_c[11] = {0, 1, 7, 22, 50, 95, 161, 252, 372, 525, 715};
static const int OFFU_h[11] = {0, 1, 7, 22, 50, 95, 161, 252, 372, 525, 715};

// ================= HOST table generation (runs at capture time only) =========
static double h_fact[19];

static double h_wig(int l, int mp, int m, double cb, double sb) {
    double pref = sqrt(h_fact[l + m] * h_fact[l - m] * h_fact[l + mp] * h_fact[l - mp]);
    int smin = (m - mp) > 0 ? (m - mp) : 0;
    int smax = (l + m) < (l - mp) ? (l + m) : (l - mp);
    double tot = 0.0;
    for (int s = smin; s <= smax; s++) {
        double den = h_fact[l + m - s] * h_fact[s] * h_fact[mp - m + s] * h_fact[l - mp - s];
        double t = pow(cb, (double)(2 * l + m - mp - 2 * s)) * pow(sb, (double)(mp - m + 2 * s)) / den;
        tot += ((mp - m + s) & 1) ? -t : t;
    }
    return pref * tot;
}

static float host_tab[TAB_LEN];

static void h_build_tables() {
    h_fact[0] = 1.0;
    for (int j = 1; j < 19; j++) h_fact[j] = h_fact[j - 1] * (double)j;

    double wq[60];
    for (int j = 0; j < 60; j++) {
        double beta = PI_D * (2 * j + 1) / 120.0;
        double s = 0.0;
        for (int k = 0; k < 30; k++)
            s += sin((double)(2 * j + 1) * (2 * k + 1) * PI_D / 120.0) / (double)(2 * k + 1);
        wq[j] = (2.0 / 30.0) * sin(beta) * s;
    }

    for (int k = 0; k < 20; k++) {
        double beta = PI_D * (2 * k + 1) / 40.0;
        double cb = cos(beta * 0.5), sb = sin(beta * 0.5);
        for (int l = 0; l < 10; l++) {
            int L = 2 * l + 1;
            for (int u = 0; u <= l; u++)
                for (int vi = 0; vi < L; vi++) {
                    int idx = OFFU_h[l] + u * L + vi;
                    host_tab[OFF_D + k * 715 + idx] =
                        (float)(h_wig(l, u, vi - l, cb, sb) * (double)L);
                }
        }
    }

    for (int k = 0; k < 60; k++) {
        double beta = PI_D * (2 * k + 1) / 120.0;
        double cb = cos(beta * 0.5), sb = sin(beta * 0.5);
        for (int l = 0; l < 10; l++)
            for (int m = 0; m <= l; m++)
                host_tab[OFF_W + k * 55 + l * (l + 1) / 2 + m] =
                    (float)(wq[k] * h_wig(l, m, 0, cb, sb));
    }

    {
        double beta = PI_D / 160.0;
        double cb = cos(beta * 0.5), sb = sin(beta * 0.5);
        for (int l = 0; l < 10; l++)
            for (int m = -l; m <= l; m++) {
                int s = l * l + l + m;
                double d0 = h_wig(l, m, 0, cb, sb);
                for (int g = 0; g < 6; g++) {
                    double ga = 2.0 * PI_D * (double)g / 6.0;
                    host_tab[OFF_KFT + (s * 6 + g) * 2 + 0] = (float)(d0 * cos((double)m * ga));
                    host_tab[OFF_KFT + (s * 6 + g) * 2 + 1] = (float)(-d0 * sin((double)m * ga));
                }
            }
    }

    for (int a = 0; a < 60; a++)
        for (int m = 0; m < 10; m++) {
            double th = -2.0 * PI_D * (double)a * (double)m / 60.0;
            host_tab[OFF_E60 + (a * 10 + m) * 2 + 0] = (float)cos(th);
            host_tab[OFF_E60 + (a * 10 + m) * 2 + 1] = (float)sin(th);
        }

    for (int vi = 0; vi < 19; vi++)
        for (int q = 0; q < 20; q++) {
            double th = 2.0 * PI_D * (double)q * (double)(vi - 9) / 20.0;
            host_tab[OFF_E20T + (vi * 20 + q) * 2 + 0] = (float)cos(th);
            host_tab[OFF_E20T + (vi * 20 + q) * 2 + 1] = (float)sin(th);
        }

    for (int p = 0; p < 20; p++)
        for (int u = 1; u <= 9; u++) {
            double th = 2.0 * PI_D * (double)p * (double)u / 20.0;
            host_tab[OFF_E20P + (p * 9 + u - 1) * 2 + 0] = (float)(2.0 * cos(th));
            host_tab[OFF_E20P + (p * 9 + u - 1) * 2 + 1] = (float)(2.0 * sin(th));
        }
}

// ================= stage 1: fhat[b][i][s] ====================================
__global__ __launch_bounds__(128) void k_fhat(const float* __restrict__ x) {
    __shared__ float  xsT[60 * 61];   // [a][k], pitch 61 = conflict-free
    __shared__ float2 xf2[600];       // [k][m], m=0..9
    __shared__ float2 e60[600];       // [a][m]
    int bi = blockIdx.x;   // b*2 + i
    const float* xp = x + (size_t)bi * 3600;
    const float2* E60g = (const float2*)(TAB_d + OFF_E60);
    for (int t = threadIdx.x; t < 3600; t += 128) {
        int k = t / 60, a = t % 60;
        xsT[a * 61 + k] = xp[t];
    }
    for (int t = threadIdx.x; t < 600; t += 128) e60[t] = E60g[t];
    __syncthreads();
    for (int t = threadIdx.x; t < 600; t += 128) {
        int mi = t / 60, k = t % 60;
        float re = 0.f, im = 0.f;
        #pragma unroll 4
        for (int a = 0; a < 60; a++) {
            float xv = xsT[a * 61 + k];
            float2 e = e60[a * 10 + mi];
            re += xv * e.x; im += xv * e.y;
        }
        xf2[k * 10 + mi] = make_float2(re, im);
    }
    __syncthreads();
    if (threadIdx.x < 55) {
        int t = threadIdx.x;
        int l = 0;
        #pragma unroll
        for (int j = 1; j < 10; j++) if (j * (j + 1) / 2 <= t) l = j;
        int m = t - l * (l + 1) / 2;
        float re = 0.f, im = 0.f;
        #pragma unroll 4
        for (int k = 0; k < 60; k++) {
            float w = TAB_d[OFF_W + k * 55 + t];
            float2 v = xf2[k * 10 + m];
            re += w * v.x; im += w * v.y;
        }
        FHAT_d[bi * 100 + l * l + l + m] = make_float2(re, im);
        if (m > 0) {
            float sg = (m & 1) ? -1.f : 1.f;
            FHAT_d[bi * 100 + l * l + l - m] = make_float2(sg * re, -sg * im);
        }
    }
}

// ================= stage 2: conj(yhat)*SCALING ===============================
__global__ void k_yhat(const float* __restrict__ kern) {
    __shared__ float ks[60];
    if (threadIdx.x < 60) ks[threadIdx.x] = kern[threadIdx.x];
    __syncthreads();
    const float2* KFT = (const float2*)(TAB_d + OFF_KFT);
    float SC = (float)(1.0 / sqrt(6.0 * 2.0 * 10000.0 / 900.0));
    for (int tt = threadIdx.x; tt < 1000; tt += blockDim.x) {
        int s = tt % 100; int io = tt / 100; int i = io % 2; int o = io / 2;
        float re = 0.f, im = 0.f;
        #pragma unroll
        for (int g = 0; g < 6; g++) {
            float kv = ks[(i * 5 + o) * 6 + g];
            float2 kf = KFT[s * 6 + g];
            re += kv * kf.x; im += kv * kf.y;
        }
        YC_d[(o * 2 + i) * 100 + s] = make_float2(re * SC, -im * SC);
    }
}

// ================= stage 3: main — z(u>=0), k-parallel chunked pipeline ======
#define KCH 5   // k-chunk size; 4 chunks of 5

__global__ __launch_bounds__(256) void k_main(const float* __restrict__ bias,
                                              float* __restrict__ out) {
    __shared__ float2 Fs[200];
    __shared__ float2 Ys[200];
    __shared__ float2 zs[715];          // packed u>=0
    __shared__ float2 e20t[380];        // [vi][q]
    __shared__ float2 e20p[180];        // [p][u-1], pre-doubled
    __shared__ float2 Ss[KCH * 190];    // [kk][u][vi]
    __shared__ float2 Gs[KCH * 200];    // [kk][u][q]
    int b = blockIdx.x, o = blockIdx.y;
    int tid = threadIdx.x;
    const float2* E20Tg = (const float2*)(TAB_d + OFF_E20T);
    const float2* E20Pg = (const float2*)(TAB_d + OFF_E20P);
    for (int t = tid; t < 200; t += 256) Fs[t] = FHAT_d[b * 200 + t];
    for (int t = tid; t < 200; t += 256) Ys[t] = YC_d[o * 200 + t];
    for (int t = tid; t < 380; t += 256) e20t[t] = E20Tg[t];
    for (int t = tid; t < 180; t += 256) e20p[t] = E20Pg[t];
    __syncthreads();
    // z_l[u,v] = sum_i fhat_l[u,i] * conj(yhat_l[v,i]), u >= 0 only
    for (int t = tid; t < 715; t += 256) {
        int l = 0;
        #pragma unroll
        for (int j = 1; j < 10; j++) if (OFFU_c[j] <= t) l = j;
        int jj = t - OFFU_c[l]; int L = 2 * l + 1;
        int u = jj / L, vi = jj % L;
        int su = l * l + l + u, sv = l * l + vi;
        float2 f0 = Fs[su], f1 = Fs[100 + su], y0 = Ys[sv], y1 = Ys[100 + sv];
        float re = f0.x * y0.x - f0.y * y0.y + f1.x * y1.x - f1.y * y1.y;
        float im = f0.x * y0.y + f0.y * y0.x + f1.x * y1.y + f1.y * y1.x;
        zs[t] = make_float2(re, im);
    }
    __syncthreads();
    float bo = bias[o];
    float* outp = out + ((size_t)(b * 5 + o)) * 8000;
    for (int k0 = 0; k0 < 20; k0 += KCH) {
        // S[kk][u,v] = sum_l D[k0+kk][l,u,v] * z[l,u,v]
        for (int t = tid; t < KCH * 190; t += 256) {
            int kk = t / 190, r = t % 190;
            int u = r / 19, vi = r % 19;
            int v = vi - 9;
            int av = v < 0 ? -v : v;
            int lmin = u > av ? u : av;
            const float* Dk = TAB_d + OFF_D + (k0 + kk) * 715;
            float re = 0.f, im = 0.f;
            for (int l = lmin; l < 10; l++) {
                int idx = OFFU_c[l] + u * (2 * l + 1) + v + l;
                float d = Dk[idx];
                float2 zv = zs[idx];
                re += d * zv.x; im += d * zv.y;
            }
            Ss[t] = make_float2(re, im);
        }
        __syncthreads();
        // G[kk][u,q] = sum_v S[kk][u,v] * e^{+2 pi i q v / 20}
        for (int t = tid; t < KCH * 200; t += 256) {
            int kk = t / 200, r = t % 200;
            int u = r / 20, q = r % 20;
            float re = 0.f, im = 0.f;
            const float2* Sr = Ss + kk * 190 + u * 19;
            #pragma unroll
            for (int vi = 0; vi < 19; vi++) {
                float2 s = Sr[vi];
                float2 e = e20t[vi * 20 + q];
                re += s.x * e.x - s.y * e.y;
                im += s.x * e.y + s.y * e.x;
            }
            Gs[t] = make_float2(re, im);
        }
        __syncthreads();
        // out[k0+kk][p,q] = bias + G[kk][0,q].re + sum_{u>=1} 2*Re(E[p,u]*G[kk][u,q])
        for (int t = tid; t < KCH * 400; t += 256) {
            int kk = t / 400, r = t % 400;
            int p = r / 20, q = r % 20;
            const float2* Gk = Gs + kk * 200;
            float acc = bo + Gk[q].x;
            const float2* Ep = e20p + p * 9;
            #pragma unroll
            for (int uu = 0; uu < 9; uu++) {
                float2 e = Ep[uu];
                float2 g = Gk[(uu + 1) * 20 + q];
                acc += e.x * g.x - e.y * g.y;   // e pre-scaled by 2
            }
            outp[k0 * 400 + t] = acc;
        }
        __syncthreads();
    }
}

// ================= launch ====================================================
extern "C" void kernel_launch(void* const* d_in, const int* in_sizes, int n_in,
                              void* d_out, int out_size) {
    const float* x    = (const float*)d_in[0];  // (512, 2, 60, 60)
    const float* kern = (const float*)d_in[1];  // (2, 5, 6)
    const float* bias = (const float*)d_in[2];  // (5)
    float* out = (float*)d_out;                 // (512, 5, 20, 20, 20)

    h_build_tables();
    cudaMemcpyToSymbolAsync(TAB_d, host_tab, sizeof(float) * TAB_LEN, 0,
                            cudaMemcpyHostToDevice, 0);

    k_fhat<<<1024, 128>>>(x);
    k_yhat<<<1, 256>>>(kern);
    dim3 g(512, 5);
    k_main<<<g, 256>>>(bias, out);
}

// round 6
// speedup vs baseline: 2.7974x; 1.3506x over previous
#include <cuda_runtime.h>
#include <math.h>
#include <string.h>

#define PI_D 3.141592653589793238462643383279502884

typedef unsigned long long ull;

// ---------------- packed table layout (floats) ----------------
// OFF_D2   : D splat (d,d) per (k, packed idx)           : 20*715*2 = 28600
// OFF_W    : quadrature * wigner d_{m,0}, m>=0 packed    : 60*55    = 3300
// OFF_KFT  : kernel FT basis float2 [s][g]               : 100*6*2  = 1200
// OFF_E60  : float2 [a][m] e^{-2pi i a m/60}, m=0..9     : 60*10*2  = 1200
// OFF_E20Q : float4 [vi][q] (ex,ey,-ey,ex)               : 19*20*4  = 1520
// OFF_E20P : float4 [p][uu] (2ex,2ex,-2ey,-2ey), u=uu+1  : 20*9*4   = 720
#define OFF_D2   0
#define OFF_W    28600
#define OFF_KFT  31900
#define OFF_E60  33100
#define OFF_E20Q 34300
#define OFF_E20P 35820
#define TAB_LEN  36540

__device__ __align__(16) float TAB_d[TAB_LEN];
__device__ float2 FHAT_d[512 * 2 * 100];
__device__ float2 YC_d[5 * 2 * 100];    // conj(yhat)*SCALING, [o][i][s]

// OFFU[l] = sum_{j<l} (j+1)(2j+1)  (u>=0 packed layout)
__constant__ int OFFU_c[11] = {0, 1, 7, 22, 50, 95, 161, 252, 372, 525, 715};
static const int OFFU_h[11] = {0, 1, 7, 22, 50, 95, 161, 252, 372, 525, 715};

// ---------------- packed f32x2 PTX helpers ----------------
#define FMA2(d, a, b, c) \
    asm("fma.rn.f32x2 %0, %1, %2, %3;" : "=l"(d) : "l"(a), "l"(b), "l"(c))
#define ADD2(d, a, b) \
    asm("add.rn.f32x2 %0, %1, %2;" : "=l"(d) : "l"(a), "l"(b))
#define PACK2(d, lo, hi) \
    asm("mov.b64 %0, {%1, %2};" : "=l"(d) : "r"(__float_as_uint(lo)), "r"(__float_as_uint(hi)))
#define UNPACK2(lo, hi, v) \
    do { unsigned _ulo, _uhi; \
         asm("mov.b64 {%0, %1}, %2;" : "=r"(_ulo), "=r"(_uhi) : "l"(v)); \
         lo = __uint_as_float(_ulo); hi = __uint_as_float(_uhi); } while (0)

// ================= HOST table generation (capture time only) =================
static double h_fact[19];

static double h_wig(int l, int mp, int m, double cb, double sb) {
    double pref = sqrt(h_fact[l + m] * h_fact[l - m] * h_fact[l + mp] * h_fact[l - mp]);
    int smin = (m - mp) > 0 ? (m - mp) : 0;
    int smax = (l + m) < (l - mp) ? (l + m) : (l - mp);
    double tot = 0.0;
    for (int s = smin; s <= smax; s++) {
        double den = h_fact[l + m - s] * h_fact[s] * h_fact[mp - m + s] * h_fact[l - mp - s];
        double t = pow(cb, (double)(2 * l + m - mp - 2 * s)) * pow(sb, (double)(mp - m + 2 * s)) / den;
        tot += ((mp - m + s) & 1) ? -t : t;
    }
    return pref * tot;
}

static float host_tab[TAB_LEN];

static void h_build_tables() {
    h_fact[0] = 1.0;
    for (int j = 1; j < 19; j++) h_fact[j] = h_fact[j - 1] * (double)j;

    double wq[60];
    for (int j = 0; j < 60; j++) {
        double beta = PI_D * (2 * j + 1) / 120.0;
        double s = 0.0;
        for (int k = 0; k < 30; k++)
            s += sin((double)(2 * j + 1) * (2 * k + 1) * PI_D / 120.0) / (double)(2 * k + 1);
        wq[j] = (2.0 / 30.0) * sin(beta) * s;
    }

    // D splat (d,d): per (k, [l,u>=0,v]) * (2l+1)
    for (int k = 0; k < 20; k++) {
        double beta = PI_D * (2 * k + 1) / 40.0;
        double cb = cos(beta * 0.5), sb = sin(beta * 0.5);
        for (int l = 0; l < 10; l++) {
            int L = 2 * l + 1;
            for (int u = 0; u <= l; u++)
                for (int vi = 0; vi < L; vi++) {
                    int idx = OFFU_h[l] + u * L + vi;
                    float d = (float)(h_wig(l, u, vi - l, cb, sb) * (double)L);
                    host_tab[OFF_D2 + (k * 715 + idx) * 2 + 0] = d;
                    host_tab[OFF_D2 + (k * 715 + idx) * 2 + 1] = d;
                }
        }
    }

    for (int k = 0; k < 60; k++) {
        double beta = PI_D * (2 * k + 1) / 120.0;
        double cb = cos(beta * 0.5), sb = sin(beta * 0.5);
        for (int l = 0; l < 10; l++)
            for (int m = 0; m <= l; m++)
                host_tab[OFF_W + k * 55 + l * (l + 1) / 2 + m] =
                    (float)(wq[k] * h_wig(l, m, 0, cb, sb));
    }

    {
        double beta = PI_D / 160.0;
        double cb = cos(beta * 0.5), sb = sin(beta * 0.5);
        for (int l = 0; l < 10; l++)
            for (int m = -l; m <= l; m++) {
                int s = l * l + l + m;
                double d0 = h_wig(l, m, 0, cb, sb);
                for (int g = 0; g < 6; g++) {
                    double ga = 2.0 * PI_D * (double)g / 6.0;
                    host_tab[OFF_KFT + (s * 6 + g) * 2 + 0] = (float)(d0 * cos((double)m * ga));
                    host_tab[OFF_KFT + (s * 6 + g) * 2 + 1] = (float)(-d0 * sin((double)m * ga));
                }
            }
    }

    for (int a = 0; a < 60; a++)
        for (int m = 0; m < 10; m++) {
            double th = -2.0 * PI_D * (double)a * (double)m / 60.0;
            host_tab[OFF_E60 + (a * 10 + m) * 2 + 0] = (float)cos(th);
            host_tab[OFF_E60 + (a * 10 + m) * 2 + 1] = (float)sin(th);
        }

    // E20Q[vi][q] = (ex, ey, -ey, ex), e = e^{+2 pi i q (vi-9)/20}
    for (int vi = 0; vi < 19; vi++)
        for (int q = 0; q < 20; q++) {
            double th = 2.0 * PI_D * (double)q * (double)(vi - 9) / 20.0;
            float ex = (float)cos(th), ey = (float)sin(th);
            int base = OFF_E20Q + (vi * 20 + q) * 4;
            host_tab[base + 0] = ex;  host_tab[base + 1] = ey;
            host_tab[base + 2] = -ey; host_tab[base + 3] = ex;
        }

    // E20P[p][uu] = (2ex, 2ex, -2ey, -2ey), e = e^{+2 pi i p (uu+1)/20}
    for (int p = 0; p < 20; p++)
        for (int uu = 0; uu < 9; uu++) {
            double th = 2.0 * PI_D * (double)p * (double)(uu + 1) / 20.0;
            float ex = (float)(2.0 * cos(th)), ey = (float)(2.0 * sin(th));
            int base = OFF_E20P + (p * 9 + uu) * 4;
            host_tab[base + 0] = ex;  host_tab[base + 1] = ex;
            host_tab[base + 2] = -ey; host_tab[base + 3] = -ey;
        }
}

// ================= stage 1: fhat[b][i][s] (m-paired, f32x2) ==================
__global__ __launch_bounds__(128) void k_fhat(const float* __restrict__ x) {
    __shared__ __align__(16) float  xsT[60 * 61];  // [a][k], pitch 61
    __shared__ __align__(16) float2 xf2[600];      // [k][m]
    __shared__ __align__(16) float2 e60[600];      // [a][m], m-adjacent
    int bi = blockIdx.x;   // b*2 + i
    const float* xp = x + (size_t)bi * 3600;
    const float2* E60g = (const float2*)(TAB_d + OFF_E60);
    for (int t = threadIdx.x; t < 3600; t += 128) {
        int k = t / 60, a = t % 60;
        xsT[a * 61 + k] = xp[t];
    }
    for (int t = threadIdx.x; t < 600; t += 128) e60[t] = E60g[t];
    __syncthreads();
    // items: (mp, k), mp = m-pair 0..4, each covers m = 2mp, 2mp+1
    for (int t = threadIdx.x; t < 300; t += 128) {
        int mp = t / 60, k = t % 60;
        ull acc0 = 0, acc1 = 0;
        #pragma unroll 4
        for (int a = 0; a < 60; a++) {
            float xv = xsT[a * 61 + k];
            ull xv2; PACK2(xv2, xv, xv);
            const ulonglong2 e2 = *reinterpret_cast<const ulonglong2*>(&e60[a * 10 + 2 * mp]);
            FMA2(acc0, xv2, e2.x, acc0);
            FMA2(acc1, xv2, e2.y, acc1);
        }
        float r0, i0, r1, i1;
        UNPACK2(r0, i0, acc0);
        UNPACK2(r1, i1, acc1);
        xf2[k * 10 + 2 * mp]     = make_float2(r0, i0);
        xf2[k * 10 + 2 * mp + 1] = make_float2(r1, i1);
    }
    __syncthreads();
    if (threadIdx.x < 55) {
        int t = threadIdx.x;
        int l = 0;
        #pragma unroll
        for (int j = 1; j < 10; j++) if (j * (j + 1) / 2 <= t) l = j;
        int m = t - l * (l + 1) / 2;
        float re = 0.f, im = 0.f;
        #pragma unroll 4
        for (int k = 0; k < 60; k++) {
            float w = TAB_d[OFF_W + k * 55 + t];
            float2 v = xf2[k * 10 + m];
            re += w * v.x; im += w * v.y;
        }
        FHAT_d[bi * 100 + l * l + l + m] = make_float2(re, im);
        if (m > 0) {
            float sg = (m & 1) ? -1.f : 1.f;
            FHAT_d[bi * 100 + l * l + l - m] = make_float2(sg * re, -sg * im);
        }
    }
}

// ================= stage 2: conj(yhat)*SCALING ===============================
__global__ void k_yhat(const float* __restrict__ kern) {
    __shared__ float ks[60];
    if (threadIdx.x < 60) ks[threadIdx.x] = kern[threadIdx.x];
    __syncthreads();
    const float2* KFT = (const float2*)(TAB_d + OFF_KFT);
    float SC = (float)(1.0 / sqrt(6.0 * 2.0 * 10000.0 / 900.0));
    for (int tt = threadIdx.x; tt < 1000; tt += blockDim.x) {
        int s = tt % 100; int io = tt / 100; int i = io % 2; int o = io / 2;
        float re = 0.f, im = 0.f;
        #pragma unroll
        for (int g = 0; g < 6; g++) {
            float kv = ks[(i * 5 + o) * 6 + g];
            float2 kf = KFT[s * 6 + g];
            re += kv * kf.x; im += kv * kf.y;
        }
        YC_d[(o * 2 + i) * 100 + s] = make_float2(re * SC, -im * SC);
    }
}

// ================= stage 3: main (f32x2 + kk register blocking) ==============
#define KCH 4   // 5 chunks of 4

__global__ __launch_bounds__(256) void k_main(const float* __restrict__ bias,
                                              float* __restrict__ out) {
    __shared__ __align__(16) float2 Fs[200];
    __shared__ __align__(16) float2 Ys[200];
    __shared__ __align__(16) float2 zs[715];        // packed u>=0, (re,im)
    __shared__ __align__(16) float4 e20q[380];      // [vi][q] (ex,ey,-ey,ex)
    __shared__ __align__(16) float4 e20p[180];      // [p][uu] (2ex,2ex,-2ey,-2ey)
    __shared__ __align__(16) float2 Ssx[190 * KCH]; // [(u,vi)][kk] splat(re)
    __shared__ __align__(16) float2 Ssy[190 * KCH]; // [(u,vi)][kk] splat(im)
    __shared__ __align__(16) float  Gre[KCH * 200]; // [kk][u][q]
    __shared__ __align__(16) float  Gim[KCH * 200];
    int b = blockIdx.x, o = blockIdx.y;
    int tid = threadIdx.x;
    for (int t = tid; t < 200; t += 256) Fs[t] = FHAT_d[b * 200 + t];
    for (int t = tid; t < 200; t += 256) Ys[t] = YC_d[o * 200 + t];
    {
        const float4* EQ = (const float4*)(TAB_d + OFF_E20Q);
        const float4* EP = (const float4*)(TAB_d + OFF_E20P);
        for (int t = tid; t < 380; t += 256) e20q[t] = EQ[t];
        for (int t = tid; t < 180; t += 256) e20p[t] = EP[t];
    }
    __syncthreads();
    // z_l[u,v] = sum_i fhat_l[u,i] * conj(yhat_l[v,i]), u >= 0 only
    for (int t = tid; t < 715; t += 256) {
        int l = 0;
        #pragma unroll
        for (int j = 1; j < 10; j++) if (OFFU_c[j] <= t) l = j;
        int jj = t - OFFU_c[l]; int L = 2 * l + 1;
        int u = jj / L, vi = jj % L;
        int su = l * l + l + u, sv = l * l + vi;
        float2 f0 = Fs[su], f1 = Fs[100 + su], y0 = Ys[sv], y1 = Ys[100 + sv];
        float re = f0.x * y0.x - f0.y * y0.y + f1.x * y1.x - f1.y * y1.y;
        float im = f0.x * y0.y + f0.y * y0.x + f1.x * y1.y + f1.y * y1.x;
        zs[t] = make_float2(re, im);
    }
    __syncthreads();
    float bo = bias[o];
    ull bo2; PACK2(bo2, bo, bo);
    float* outp = out + ((size_t)(b * 5 + o)) * 8000;
    for (int k0 = 0; k0 < 20; k0 += KCH) {
        // ---- S-phase: items (u,vi), 190 threads, KCH k-slices in registers ----
        if (tid < 190) {
            int u = tid / 19, vi = tid % 19;
            int v = vi - 9;
            int av = v < 0 ? -v : v;
            int lmin = u > av ? u : av;
            ull acc[KCH];
            #pragma unroll
            for (int kk = 0; kk < KCH; kk++) acc[kk] = 0ull;
            const ull* D2 = (const ull*)(TAB_d + OFF_D2);
            for (int l = lmin; l < 10; l++) {
                int idx = OFFU_c[l] + u * (2 * l + 1) + v + l;
                ull z2 = *reinterpret_cast<const ull*>(&zs[idx]);
                #pragma unroll
                for (int kk = 0; kk < KCH; kk++) {
                    ull d2 = D2[(k0 + kk) * 715 + idx];
                    FMA2(acc[kk], d2, z2, acc[kk]);
                }
            }
            #pragma unroll
            for (int kk = 0; kk < KCH; kk++) {
                float re, im;
                UNPACK2(re, im, acc[kk]);
                Ssx[tid * KCH + kk] = make_float2(re, re);
                Ssy[tid * KCH + kk] = make_float2(im, im);
            }
        }
        __syncthreads();
        // ---- G-phase: items (q,u), 200 threads ----
        if (tid < 200) {
            int q = tid % 20, u = tid / 20;
            ull acc[KCH];
            #pragma unroll
            for (int kk = 0; kk < KCH; kk++) acc[kk] = 0ull;
            for (int vi = 0; vi < 19; vi++) {
                const ulonglong2 e2 = *reinterpret_cast<const ulonglong2*>(&e20q[vi * 20 + q]);
                int sb = (u * 19 + vi) * KCH;
                const ulonglong2 sx01 = *reinterpret_cast<const ulonglong2*>(&Ssx[sb]);
                const ulonglong2 sx23 = *reinterpret_cast<const ulonglong2*>(&Ssx[sb + 2]);
                const ulonglong2 sy01 = *reinterpret_cast<const ulonglong2*>(&Ssy[sb]);
                const ulonglong2 sy23 = *reinterpret_cast<const ulonglong2*>(&Ssy[sb + 2]);
                FMA2(acc[0], sx01.x, e2.x, acc[0]);
                FMA2(acc[0], sy01.x, e2.y, acc[0]);
                FMA2(acc[1], sx01.y, e2.x, acc[1]);
                FMA2(acc[1], sy01.y, e2.y, acc[1]);
                FMA2(acc[2], sx23.x, e2.x, acc[2]);
                FMA2(acc[2], sy23.x, e2.y, acc[2]);
                FMA2(acc[3], sx23.y, e2.x, acc[3]);
                FMA2(acc[3], sy23.y, e2.y, acc[3]);
            }
            #pragma unroll
            for (int kk = 0; kk < KCH; kk++) {
                float re, im;
                UNPACK2(re, im, acc[kk]);
                Gre[kk * 200 + u * 20 + q] = re;
                Gim[kk * 200 + u * 20 + q] = im;
            }
        }
        __syncthreads();
        // ---- out-phase: items (p, q-pair), 200 threads, 2 q's per thread ----
        if (tid < 200) {
            int q2 = tid % 10, p = tid / 10;
            int qof = 2 * q2;
            ull acc[KCH];
            #pragma unroll
            for (int kk = 0; kk < KCH; kk++) {
                ull g0 = *reinterpret_cast<const ull*>(&Gre[kk * 200 + qof]);
                ADD2(acc[kk], bo2, g0);
            }
            #pragma unroll
            for (int uu = 0; uu < 9; uu++) {
                const ulonglong2 e2 = *reinterpret_cast<const ulonglong2*>(&e20p[p * 9 + uu]);
                int gb = (uu + 1) * 20 + qof;
                #pragma unroll
                for (int kk = 0; kk < KCH; kk++) {
                    ull gre2 = *reinterpret_cast<const ull*>(&Gre[kk * 200 + gb]);
                    ull gim2 = *reinterpret_cast<const ull*>(&Gim[kk * 200 + gb]);
                    FMA2(acc[kk], e2.x, gre2, acc[kk]);
                    FMA2(acc[kk], e2.y, gim2, acc[kk]);
                }
            }
            #pragma unroll
            for (int kk = 0; kk < KCH; kk++)
                *reinterpret_cast<ull*>(&outp[(k0 + kk) * 400 + p * 20 + qof]) = acc[kk];
        }
        __syncthreads();
    }
}

// ================= launch ====================================================
extern "C" void kernel_launch(void* const* d_in, const int* in_sizes, int n_in,
                              void* d_out, int out_size) {
    const float* x    = (const float*)d_in[0];  // (512, 2, 60, 60)
    const float* kern = (const float*)d_in[1];  // (2, 5, 6)
    const float* bias = (const float*)d_in[2];  // (5)
    float* out = (float*)d_out;                 // (512, 5, 20, 20, 20)

    h_build_tables();
    cudaMemcpyToSymbolAsync(TAB_d, host_tab, sizeof(float) * TAB_LEN, 0,
                            cudaMemcpyHostToDevice, 0);

    k_fhat<<<1024, 128>>>(x);
    k_yhat<<<1, 256>>>(kern);
    dim3 g(512, 5);
    k_main<<<g, 256>>>(bias, out);
}

// round 7
// speedup vs baseline: 2.9432x; 1.0521x over previous
#include <cuda_runtime.h>
#include <math.h>
#include <string.h>

#define PI_D 3.141592653589793238462643383279502884

typedef unsigned long long ull;

// ---------------- packed table layout (floats) ----------------
// OFF_D2   : D splat (d,d) per (k, packed idx)           : 20*715*2 = 28600
// OFF_W    : quadrature * wigner d_{m,0}, m>=0 packed    : 60*55    = 3300
// OFF_KFT  : kernel FT basis float2 [s][g]               : 100*6*2  = 1200
// OFF_E60  : float2 [a][m] e^{-2pi i a m/60}, m=0..9     : 60*10*2  = 1200
// OFF_E4Q  : float4 [vp-1][q] (ex,ex,ey,ey), q=0..9      : 9*10*4   = 360
// OFF_E20P : float4 [p][uu-1] (2ex,2ex,-2ey,-2ey)        : 10*9*4   = 360
#define OFF_D2   0
#define OFF_W    28600
#define OFF_KFT  31900
#define OFF_E60  33100
#define OFF_E4Q  34300
#define OFF_E20P 34660
#define TAB_LEN  35020

#define SIGN2 0x8000000080000000ULL

__device__ __align__(16) float TAB_d[TAB_LEN];
__device__ float2 FHAT_d[512 * 2 * 100];
__device__ float2 YC_d[5 * 2 * 100];    // conj(yhat)*SCALING, [o][i][s]

// OFFU[l] = sum_{j<l} (j+1)(2j+1)  (u>=0 packed layout)
__constant__ int OFFU_c[11] = {0, 1, 7, 22, 50, 95, 161, 252, 372, 525, 715};
static const int OFFU_h[11] = {0, 1, 7, 22, 50, 95, 161, 252, 372, 525, 715};

// ---------------- packed f32x2 PTX helpers ----------------
#define FMA2(d, a, b, c) \
    asm("fma.rn.f32x2 %0, %1, %2, %3;" : "=l"(d) : "l"(a), "l"(b), "l"(c))
#define ADD2(d, a, b) \
    asm("add.rn.f32x2 %0, %1, %2;" : "=l"(d) : "l"(a), "l"(b))
#define PACK2(d, lo, hi) \
    asm("mov.b64 %0, {%1, %2};" : "=l"(d) : "r"(__float_as_uint(lo)), "r"(__float_as_uint(hi)))
#define UNPACK2(lo, hi, v) \
    do { unsigned _ulo, _uhi; \
         asm("mov.b64 {%0, %1}, %2;" : "=r"(_ulo), "=r"(_uhi) : "l"(v)); \
         lo = __uint_as_float(_ulo); hi = __uint_as_float(_uhi); } while (0)

// ================= HOST table generation (capture time only) =================
static double h_fact[19];

static double h_wig(int l, int mp, int m, double cb, double sb) {
    double pref = sqrt(h_fact[l + m] * h_fact[l - m] * h_fact[l + mp] * h_fact[l - mp]);
    int smin = (m - mp) > 0 ? (m - mp) : 0;
    int smax = (l + m) < (l - mp) ? (l + m) : (l - mp);
    double tot = 0.0;
    for (int s = smin; s <= smax; s++) {
        double den = h_fact[l + m - s] * h_fact[s] * h_fact[mp - m + s] * h_fact[l - mp - s];
        double t = pow(cb, (double)(2 * l + m - mp - 2 * s)) * pow(sb, (double)(mp - m + 2 * s)) / den;
        tot += ((mp - m + s) & 1) ? -t : t;
    }
    return pref * tot;
}

static float host_tab[TAB_LEN];

static void h_build_tables() {
    h_fact[0] = 1.0;
    for (int j = 1; j < 19; j++) h_fact[j] = h_fact[j - 1] * (double)j;

    double wq[60];
    for (int j = 0; j < 60; j++) {
        double beta = PI_D * (2 * j + 1) / 120.0;
        double s = 0.0;
        for (int k = 0; k < 30; k++)
            s += sin((double)(2 * j + 1) * (2 * k + 1) * PI_D / 120.0) / (double)(2 * k + 1);
        wq[j] = (2.0 / 30.0) * sin(beta) * s;
    }

    // D splat (d,d): per (k, [l,u>=0,v]) * (2l+1)
    for (int k = 0; k < 20; k++) {
        double beta = PI_D * (2 * k + 1) / 40.0;
        double cb = cos(beta * 0.5), sb = sin(beta * 0.5);
        for (int l = 0; l < 10; l++) {
            int L = 2 * l + 1;
            for (int u = 0; u <= l; u++)
                for (int vi = 0; vi < L; vi++) {
                    int idx = OFFU_h[l] + u * L + vi;
                    float d = (float)(h_wig(l, u, vi - l, cb, sb) * (double)L);
                    host_tab[OFF_D2 + (k * 715 + idx) * 2 + 0] = d;
                    host_tab[OFF_D2 + (k * 715 + idx) * 2 + 1] = d;
                }
        }
    }

    for (int k = 0; k < 60; k++) {
        double beta = PI_D * (2 * k + 1) / 120.0;
        double cb = cos(beta * 0.5), sb = sin(beta * 0.5);
        for (int l = 0; l < 10; l++)
            for (int m = 0; m <= l; m++)
                host_tab[OFF_W + k * 55 + l * (l + 1) / 2 + m] =
                    (float)(wq[k] * h_wig(l, m, 0, cb, sb));
    }

    {
        double beta = PI_D / 160.0;
        double cb = cos(beta * 0.5), sb = sin(beta * 0.5);
        for (int l = 0; l < 10; l++)
            for (int m = -l; m <= l; m++) {
                int s = l * l + l + m;
                double d0 = h_wig(l, m, 0, cb, sb);
                for (int g = 0; g < 6; g++) {
                    double ga = 2.0 * PI_D * (double)g / 6.0;
                    host_tab[OFF_KFT + (s * 6 + g) * 2 + 0] = (float)(d0 * cos((double)m * ga));
                    host_tab[OFF_KFT + (s * 6 + g) * 2 + 1] = (float)(-d0 * sin((double)m * ga));
                }
            }
    }

    for (int a = 0; a < 60; a++)
        for (int m = 0; m < 10; m++) {
            double th = -2.0 * PI_D * (double)a * (double)m / 60.0;
            host_tab[OFF_E60 + (a * 10 + m) * 2 + 0] = (float)cos(th);
            host_tab[OFF_E60 + (a * 10 + m) * 2 + 1] = (float)sin(th);
        }

    // E4Q[vp-1][q] = (ex,ex,ey,ey), e = e^{+2 pi i q vp/20}, vp=1..9, q=0..9
    for (int vp = 1; vp <= 9; vp++)
        for (int q = 0; q < 10; q++) {
            double th = 2.0 * PI_D * (double)q * (double)vp / 20.0;
            float ex = (float)cos(th), ey = (float)sin(th);
            int base = OFF_E4Q + ((vp - 1) * 10 + q) * 4;
            host_tab[base + 0] = ex; host_tab[base + 1] = ex;
            host_tab[base + 2] = ey; host_tab[base + 3] = ey;
        }

    // E20P[p][uu-1] = (2ex,2ex,-2ey,-2ey), e = e^{+2 pi i p uu/20}, p=0..9, uu=1..9
    for (int p = 0; p < 10; p++)
        for (int uu = 1; uu <= 9; uu++) {
            double th = 2.0 * PI_D * (double)p * (double)uu / 20.0;
            float ex = (float)(2.0 * cos(th)), ey = (float)(2.0 * sin(th));
            int base = OFF_E20P + (p * 9 + uu - 1) * 4;
            host_tab[base + 0] = ex;  host_tab[base + 1] = ex;
            host_tab[base + 2] = -ey; host_tab[base + 3] = -ey;
        }
}

// ================= stage 1: fhat[b][i][s] (m-paired, f32x2) ==================
__global__ __launch_bounds__(128) void k_fhat(const float* __restrict__ x) {
    __shared__ __align__(16) float  xsT[60 * 61];  // [a][k], pitch 61
    __shared__ __align__(16) float2 xf2[600];      // [k][m]
    __shared__ __align__(16) float2 e60[600];      // [a][m], m-adjacent
    int bi = blockIdx.x;   // b*2 + i
    const float* xp = x + (size_t)bi * 3600;
    const float2* E60g = (const float2*)(TAB_d + OFF_E60);
    for (int t = threadIdx.x; t < 3600; t += 128) {
        int k = t / 60, a = t % 60;
        xsT[a * 61 + k] = xp[t];
    }
    for (int t = threadIdx.x; t < 600; t += 128) e60[t] = E60g[t];
    __syncthreads();
    for (int t = threadIdx.x; t < 300; t += 128) {
        int mp = t / 60, k = t % 60;
        ull acc0 = 0, acc1 = 0;
        #pragma unroll 4
        for (int a = 0; a < 60; a++) {
            float xv = xsT[a * 61 + k];
            ull xv2; PACK2(xv2, xv, xv);
            const ulonglong2 e2 = *reinterpret_cast<const ulonglong2*>(&e60[a * 10 + 2 * mp]);
            FMA2(acc0, xv2, e2.x, acc0);
            FMA2(acc1, xv2, e2.y, acc1);
        }
        float r0, i0, r1, i1;
        UNPACK2(r0, i0, acc0);
        UNPACK2(r1, i1, acc1);
        xf2[k * 10 + 2 * mp]     = make_float2(r0, i0);
        xf2[k * 10 + 2 * mp + 1] = make_float2(r1, i1);
    }
    __syncthreads();
    if (threadIdx.x < 55) {
        int t = threadIdx.x;
        int l = 0;
        #pragma unroll
        for (int j = 1; j < 10; j++) if (j * (j + 1) / 2 <= t) l = j;
        int m = t - l * (l + 1) / 2;
        float re = 0.f, im = 0.f;
        #pragma unroll 4
        for (int k = 0; k < 60; k++) {
            float w = TAB_d[OFF_W + k * 55 + t];
            float2 v = xf2[k * 10 + m];
            re += w * v.x; im += w * v.y;
        }
        FHAT_d[bi * 100 + l * l + l + m] = make_float2(re, im);
        if (m > 0) {
            float sg = (m & 1) ? -1.f : 1.f;
            FHAT_d[bi * 100 + l * l + l - m] = make_float2(sg * re, -sg * im);
        }
    }
}

// ================= stage 2: conj(yhat)*SCALING ===============================
__global__ void k_yhat(const float* __restrict__ kern) {
    __shared__ float ks[60];
    if (threadIdx.x < 60) ks[threadIdx.x] = kern[threadIdx.x];
    __syncthreads();
    const float2* KFT = (const float2*)(TAB_d + OFF_KFT);
    float SC = (float)(1.0 / sqrt(6.0 * 2.0 * 10000.0 / 900.0));
    for (int tt = threadIdx.x; tt < 1000; tt += blockDim.x) {
        int s = tt % 100; int io = tt / 100; int i = io % 2; int o = io / 2;
        float re = 0.f, im = 0.f;
        #pragma unroll
        for (int g = 0; g < 6; g++) {
            float kv = ks[(i * 5 + o) * 6 + g];
            float2 kf = KFT[s * 6 + g];
            re += kv * kf.x; im += kv * kf.y;
        }
        YC_d[(o * 2 + i) * 100 + s] = make_float2(re * SC, -im * SC);
    }
}

// ================= stage 3: main — folded symmetric pipeline ================
#define KCH 5   // 4 chunks of 5 k's

// shared layout (bytes):
//   ST   [ (u*9+vp-1)*20 + k ] x {Sp,Tm} float2 pairs : 0      .. 28800
//   S0   [ u*20 + k ] float2                          : 28800  .. 30400
//   e4q  [vp-1][q] float4                             : 30400  .. 31840
//   e20p [p][uu-1] float4                             : 31840  .. 33280
//   union:
//     phase A: Fs 33280..34880, Ys 34880..36480, zs 36480..42200
//     phase B: Gre 33280..37280, Gim 37280..41280
#define SM_BYTES 42208

__global__ __launch_bounds__(256) void k_main(const float* __restrict__ bias,
                                              float* __restrict__ out) {
    __shared__ __align__(16) char SM[SM_BYTES];
    float2* ST_s   = (float2*)(SM);
    float2* S0_s   = (float2*)(SM + 28800);
    float4* e4q_s  = (float4*)(SM + 30400);
    float4* e20p_s = (float4*)(SM + 31840);
    float2* Fs     = (float2*)(SM + 33280);
    float2* Ys     = (float2*)(SM + 34880);
    float2* zs     = (float2*)(SM + 36480);
    float*  Gre_s  = (float*)(SM + 33280);
    float*  Gim_s  = (float*)(SM + 37280);

    int b = blockIdx.x, o = blockIdx.y;
    int tid = threadIdx.x;
    for (int t = tid; t < 200; t += 256) Fs[t] = FHAT_d[b * 200 + t];
    for (int t = tid; t < 200; t += 256) Ys[t] = YC_d[o * 200 + t];
    {
        const float4* EQ = (const float4*)(TAB_d + OFF_E4Q);
        const float4* EP = (const float4*)(TAB_d + OFF_E20P);
        if (tid < 90) e4q_s[tid] = EQ[tid];
        else if (tid < 180) e20p_s[tid - 90] = EP[tid - 90];
    }
    __syncthreads();

    // ---- z-phase: z_l[u,v] = sum_i fhat_l[u,i] * conj(yhat_l[v,i]), u>=0 ----
    for (int t = tid; t < 715; t += 256) {
        int l = 0;
        #pragma unroll
        for (int j = 1; j < 10; j++) if (OFFU_c[j] <= t) l = j;
        int jj = t - OFFU_c[l]; int L = 2 * l + 1;
        int u = jj / L, vi = jj % L;
        int su = l * l + l + u, sv = l * l + vi;
        float2 f0 = Fs[su], f1 = Fs[100 + su], y0 = Ys[sv], y1 = Ys[100 + sv];
        float re = f0.x * y0.x - f0.y * y0.y + f1.x * y1.x - f1.y * y1.y;
        float im = f0.x * y0.y + f0.y * y0.x + f1.x * y1.y + f1.y * y1.x;
        zs[t] = make_float2(re, im);
    }
    __syncthreads();

    // ---- S-phase (all 20 k at once): items (u,k) v=0, and (u,vp,k) vp>=1 ----
    for (int it = tid; it < 2000; it += 256) {
        if (it < 200) {
            int u = it / 20, k = it % 20;
            const ull* D2 = (const ull*)(TAB_d + OFF_D2) + k * 715;
            ull acc = 0;
            for (int l = u; l < 10; l++) {
                int idx = OFFU_c[l] + u * (2 * l + 1) + l;   // v = 0
                ull z2 = *reinterpret_cast<const ull*>(&zs[idx]);
                FMA2(acc, D2[idx], z2, acc);
            }
            *reinterpret_cast<ull*>(&S0_s[u * 20 + k]) = acc;
        } else {
            int it2 = it - 200;
            int u = it2 / 180, rem = it2 % 180;
            int vp = rem / 20 + 1, k = rem % 20;
            int lmin = u > vp ? u : vp;
            const ull* D2 = (const ull*)(TAB_d + OFF_D2) + k * 715;
            ull accP = 0, accM = 0;
            for (int l = lmin; l < 10; l++) {
                int base = OFFU_c[l] + u * (2 * l + 1) + l;
                ull zp = *reinterpret_cast<const ull*>(&zs[base + vp]);
                ull zm = *reinterpret_cast<const ull*>(&zs[base - vp]);
                FMA2(accP, D2[base + vp], zp, accP);
                FMA2(accM, D2[base - vp], zm, accM);
            }
            float pr, pi, mr, mi;
            UNPACK2(pr, pi, accP);
            UNPACK2(mr, mi, accM);
            int sb = ((u * 9 + vp - 1) * 20 + k) * 2;
            ST_s[sb]     = make_float2(pr + mr, pi + mi);   // Sp = Sv + S-v
            ST_s[sb + 1] = make_float2(mi - pi, pr - mr);   // Tm = i*(Sv - S-v)
        }
    }
    __syncthreads();

    float bo = bias[o];
    ull bo2; PACK2(bo2, bo, bo);
    float* outp = out + ((size_t)(b * 5 + o)) * 8000;

    for (int k0 = 0; k0 < 20; k0 += KCH) {
        // ---- G-phase: thread (q 0..9, u 0..9); q-fold via parity accs ----
        if (tid < 100) {
            int q = tid % 10, u = tid / 10;
            ull acc_e[KCH], acc_o[KCH];
            #pragma unroll
            for (int kk = 0; kk < KCH; kk++) {
                acc_e[kk] = *reinterpret_cast<const ull*>(&S0_s[u * 20 + k0 + kk]);
                acc_o[kk] = 0ull;
            }
            const ulonglong2* STu = (const ulonglong2*)ST_s;
            #pragma unroll
            for (int vp = 1; vp <= 9; vp++) {
                const ulonglong2 e2 =
                    *reinterpret_cast<const ulonglong2*>(&e4q_s[(vp - 1) * 10 + q]);
                int sbase = (u * 9 + vp - 1) * 20 + k0;
                #pragma unroll
                for (int kk = 0; kk < KCH; kk++) {
                    ulonglong2 st = STu[sbase + kk];
                    if (vp & 1) {
                        FMA2(acc_o[kk], e2.x, st.x, acc_o[kk]);
                        FMA2(acc_o[kk], e2.y, st.y, acc_o[kk]);
                    } else {
                        FMA2(acc_e[kk], e2.x, st.x, acc_e[kk]);
                        FMA2(acc_e[kk], e2.y, st.y, acc_e[kk]);
                    }
                }
            }
            #pragma unroll
            for (int kk = 0; kk < KCH; kk++) {
                ull s, d;
                ADD2(s, acc_e[kk], acc_o[kk]);
                ull no = acc_o[kk] ^ SIGN2;
                ADD2(d, acc_e[kk], no);
                float gr, gi;
                UNPACK2(gr, gi, s);
                Gre_s[kk * 200 + u * 20 + q] = gr;
                Gim_s[kk * 200 + u * 20 + q] = gi;
                UNPACK2(gr, gi, d);
                Gre_s[kk * 200 + u * 20 + q + 10] = gr;
                Gim_s[kk * 200 + u * 20 + q + 10] = gi;
            }
        }
        __syncthreads();
        // ---- out-phase: thread (p 0..9, q-pair 0..9); p-fold via parity ----
        if (tid < 100) {
            int p = tid / 10, qof = (tid % 10) * 2;
            ull acc_e[KCH], acc_o[KCH];
            #pragma unroll
            for (int kk = 0; kk < KCH; kk++) {
                ull g0 = *reinterpret_cast<const ull*>(&Gre_s[kk * 200 + qof]);
                ADD2(acc_e[kk], bo2, g0);      // bias + G[0,q].re  (u=0 even)
                acc_o[kk] = 0ull;
            }
            #pragma unroll
            for (int uu = 1; uu <= 9; uu++) {
                const ulonglong2 e2 =
                    *reinterpret_cast<const ulonglong2*>(&e20p_s[p * 9 + uu - 1]);
                #pragma unroll
                for (int kk = 0; kk < KCH; kk++) {
                    ull gr = *reinterpret_cast<const ull*>(&Gre_s[kk * 200 + uu * 20 + qof]);
                    ull gi = *reinterpret_cast<const ull*>(&Gim_s[kk * 200 + uu * 20 + qof]);
                    if (uu & 1) {
                        FMA2(acc_o[kk], e2.x, gr, acc_o[kk]);
                        FMA2(acc_o[kk], e2.y, gi, acc_o[kk]);
                    } else {
                        FMA2(acc_e[kk], e2.x, gr, acc_e[kk]);
                        FMA2(acc_e[kk], e2.y, gi, acc_e[kk]);
                    }
                }
            }
            #pragma unroll
            for (int kk = 0; kk < KCH; kk++) {
                ull s, d;
                ADD2(s, acc_e[kk], acc_o[kk]);
                ull no = acc_o[kk] ^ SIGN2;
                ADD2(d, acc_e[kk], no);
                *reinterpret_cast<ull*>(&outp[(k0 + kk) * 400 + p * 20 + qof]) = s;
                *reinterpret_cast<ull*>(&outp[(k0 + kk) * 400 + (p + 10) * 20 + qof]) = d;
            }
        }
        __syncthreads();
    }
}

// ================= launch ====================================================
extern "C" void kernel_launch(void* const* d_in, const int* in_sizes, int n_in,
                              void* d_out, int out_size) {
    const float* x    = (const float*)d_in[0];  // (512, 2, 60, 60)
    const float* kern = (const float*)d_in[1];  // (2, 5, 6)
    const float* bias = (const float*)d_in[2];  // (5)
    float* out = (float*)d_out;                 // (512, 5, 20, 20, 20)

    h_build_tables();
    cudaMemcpyToSymbolAsync(TAB_d, host_tab, sizeof(float) * TAB_LEN, 0,
                            cudaMemcpyHostToDevice, 0);

    k_fhat<<<1024, 128>>>(x);
    k_yhat<<<1, 256>>>(kern);
    dim3 g(512, 5);
    k_main<<<g, 256>>>(bias, out);
}

// round 8
// speedup vs baseline: 3.1520x; 1.0709x over previous
#include <cuda_runtime.h>
#include <math.h>
#include <string.h>

#define PI_D 3.141592653589793238462643383279502884

typedef unsigned long long ull;

// ---------------- packed table layout (floats) ----------------
#define OFF_D2   0
#define OFF_W    28600
#define OFF_KFT  31900
#define OFF_E60  33100
#define OFF_E4Q  34300
#define OFF_E20P 34660
#define TAB_LEN  35020

#define SIGN2 0x8000000080000000ULL

__device__ __align__(16) float TAB_d[TAB_LEN];
__device__ float2 FHAT_d[512 * 2 * 100];

// OFFU[l] = sum_{j<l} (j+1)(2j+1)  (u>=0 packed layout)
__constant__ int OFFU_c[11] = {0, 1, 7, 22, 50, 95, 161, 252, 372, 525, 715};
static const int OFFU_h[11] = {0, 1, 7, 22, 50, 95, 161, 252, 372, 525, 715};

// ---------------- packed f32x2 PTX helpers ----------------
#define FMA2(d, a, b, c) \
    asm("fma.rn.f32x2 %0, %1, %2, %3;" : "=l"(d) : "l"(a), "l"(b), "l"(c))
#define ADD2(d, a, b) \
    asm("add.rn.f32x2 %0, %1, %2;" : "=l"(d) : "l"(a), "l"(b))
#define PACK2(d, lo, hi) \
    asm("mov.b64 %0, {%1, %2};" : "=l"(d) : "r"(__float_as_uint(lo)), "r"(__float_as_uint(hi)))
#define UNPACK2(lo, hi, v) \
    do { unsigned _ulo, _uhi; \
         asm("mov.b64 {%0, %1}, %2;" : "=r"(_ulo), "=r"(_uhi) : "l"(v)); \
         lo = __uint_as_float(_ulo); hi = __uint_as_float(_uhi); } while (0)

// ================= HOST table generation (capture time only) =================
static double h_fact[19];

static double h_wig(int l, int mp, int m, double cb, double sb) {
    double pref = sqrt(h_fact[l + m] * h_fact[l - m] * h_fact[l + mp] * h_fact[l - mp]);
    int smin = (m - mp) > 0 ? (m - mp) : 0;
    int smax = (l + m) < (l - mp) ? (l + m) : (l - mp);
    double tot = 0.0;
    for (int s = smin; s <= smax; s++) {
        double den = h_fact[l + m - s] * h_fact[s] * h_fact[mp - m + s] * h_fact[l - mp - s];
        double t = pow(cb, (double)(2 * l + m - mp - 2 * s)) * pow(sb, (double)(mp - m + 2 * s)) / den;
        tot += ((mp - m + s) & 1) ? -t : t;
    }
    return pref * tot;
}

static float host_tab[TAB_LEN];

static void h_build_tables() {
    h_fact[0] = 1.0;
    for (int j = 1; j < 19; j++) h_fact[j] = h_fact[j - 1] * (double)j;

    double wq[60];
    for (int j = 0; j < 60; j++) {
        double beta = PI_D * (2 * j + 1) / 120.0;
        double s = 0.0;
        for (int k = 0; k < 30; k++)
            s += sin((double)(2 * j + 1) * (2 * k + 1) * PI_D / 120.0) / (double)(2 * k + 1);
        wq[j] = (2.0 / 30.0) * sin(beta) * s;
    }

    // D splat (d,d): per (k, [l,u>=0,v]) * (2l+1)
    for (int k = 0; k < 20; k++) {
        double beta = PI_D * (2 * k + 1) / 40.0;
        double cb = cos(beta * 0.5), sb = sin(beta * 0.5);
        for (int l = 0; l < 10; l++) {
            int L = 2 * l + 1;
            for (int u = 0; u <= l; u++)
                for (int vi = 0; vi < L; vi++) {
                    int idx = OFFU_h[l] + u * L + vi;
                    float d = (float)(h_wig(l, u, vi - l, cb, sb) * (double)L);
                    host_tab[OFF_D2 + (k * 715 + idx) * 2 + 0] = d;
                    host_tab[OFF_D2 + (k * 715 + idx) * 2 + 1] = d;
                }
        }
    }

    for (int k = 0; k < 60; k++) {
        double beta = PI_D * (2 * k + 1) / 120.0;
        double cb = cos(beta * 0.5), sb = sin(beta * 0.5);
        for (int l = 0; l < 10; l++)
            for (int m = 0; m <= l; m++)
                host_tab[OFF_W + k * 55 + l * (l + 1) / 2 + m] =
                    (float)(wq[k] * h_wig(l, m, 0, cb, sb));
    }

    {
        double beta = PI_D / 160.0;
        double cb = cos(beta * 0.5), sb = sin(beta * 0.5);
        for (int l = 0; l < 10; l++)
            for (int m = -l; m <= l; m++) {
                int s = l * l + l + m;
                double d0 = h_wig(l, m, 0, cb, sb);
                for (int g = 0; g < 6; g++) {
                    double ga = 2.0 * PI_D * (double)g / 6.0;
                    host_tab[OFF_KFT + (s * 6 + g) * 2 + 0] = (float)(d0 * cos((double)m * ga));
                    host_tab[OFF_KFT + (s * 6 + g) * 2 + 1] = (float)(-d0 * sin((double)m * ga));
                }
            }
    }

    for (int a = 0; a < 60; a++)
        for (int m = 0; m < 10; m++) {
            double th = -2.0 * PI_D * (double)a * (double)m / 60.0;
            host_tab[OFF_E60 + (a * 10 + m) * 2 + 0] = (float)cos(th);
            host_tab[OFF_E60 + (a * 10 + m) * 2 + 1] = (float)sin(th);
        }

    // E4Q[vp-1][q] = (ex,ex,ey,ey), e = e^{+2 pi i q vp/20}
    for (int vp = 1; vp <= 9; vp++)
        for (int q = 0; q < 10; q++) {
            double th = 2.0 * PI_D * (double)q * (double)vp / 20.0;
            float ex = (float)cos(th), ey = (float)sin(th);
            int base = OFF_E4Q + ((vp - 1) * 10 + q) * 4;
            host_tab[base + 0] = ex; host_tab[base + 1] = ex;
            host_tab[base + 2] = ey; host_tab[base + 3] = ey;
        }

    // E20P[p][uu-1] = (2ex,2ex,-2ey,-2ey), e = e^{+2 pi i p uu/20}
    for (int p = 0; p < 10; p++)
        for (int uu = 1; uu <= 9; uu++) {
            double th = 2.0 * PI_D * (double)p * (double)uu / 20.0;
            float ex = (float)(2.0 * cos(th)), ey = (float)(2.0 * sin(th));
            int base = OFF_E20P + (p * 9 + uu - 1) * 4;
            host_tab[base + 0] = ex;  host_tab[base + 1] = ex;
            host_tab[base + 2] = -ey; host_tab[base + 3] = -ey;
        }
}

// ================= stage 1: fhat[b][i][s] ====================================
__global__ __launch_bounds__(128) void k_fhat(const float* __restrict__ x) {
    __shared__ __align__(16) float  xsT[60 * 61];  // [a][k], pitch 61
    __shared__ __align__(16) float2 xf2[600];      // [k][m]
    __shared__ __align__(16) float2 e60[600];      // [a][m]
    int bi = blockIdx.x;   // b*2 + i
    const float* xp = x + (size_t)bi * 3600;
    const float2* E60g = (const float2*)(TAB_d + OFF_E60);
    for (int t = threadIdx.x; t < 3600; t += 128) {
        int k = t / 60, a = t % 60;
        xsT[a * 61 + k] = xp[t];
    }
    for (int t = threadIdx.x; t < 600; t += 128) e60[t] = E60g[t];
    __syncthreads();
    for (int t = threadIdx.x; t < 300; t += 128) {
        int mp = t / 60, k = t % 60;
        ull acc0 = 0, acc1 = 0;
        #pragma unroll 4
        for (int a = 0; a < 60; a++) {
            float xv = xsT[a * 61 + k];
            ull xv2; PACK2(xv2, xv, xv);
            const ulonglong2 e2 = *reinterpret_cast<const ulonglong2*>(&e60[a * 10 + 2 * mp]);
            FMA2(acc0, xv2, e2.x, acc0);
            FMA2(acc1, xv2, e2.y, acc1);
        }
        float r0, i0, r1, i1;
        UNPACK2(r0, i0, acc0);
        UNPACK2(r1, i1, acc1);
        xf2[k * 10 + 2 * mp]     = make_float2(r0, i0);
        xf2[k * 10 + 2 * mp + 1] = make_float2(r1, i1);
    }
    __syncthreads();
    // final contraction: 110 threads (sp x half), shfl-pair reduce
    {
        int t = threadIdx.x;
        int sp = t >> 1;
        if (sp > 54) sp = 54;          // clamp; keeps warp converged for shfl
        int half = t & 1;
        int l = 0;
        #pragma unroll
        for (int j = 1; j < 10; j++) if (j * (j + 1) / 2 <= sp) l = j;
        int m = sp - l * (l + 1) / 2;
        float re = 0.f, im = 0.f;
        int k0 = half * 30;
        #pragma unroll 5
        for (int k = k0; k < k0 + 30; k++) {
            float w = TAB_d[OFF_W + k * 55 + sp];
            float2 v = xf2[k * 10 + m];
            re += w * v.x; im += w * v.y;
        }
        re += __shfl_xor_sync(0xFFFFFFFFu, re, 1);
        im += __shfl_xor_sync(0xFFFFFFFFu, im, 1);
        if (half == 0 && t < 110) {
            FHAT_d[bi * 100 + l * l + l + m] = make_float2(re, im);
            if (m > 0) {
                float sg = (m & 1) ? -1.f : 1.f;
                FHAT_d[bi * 100 + l * l + l - m] = make_float2(sg * re, -sg * im);
            }
        }
    }
}

// ================= stage 3: main — low-smem, high-residency pipeline =========
#define KCH 4   // 5 chunks of 4 k's

// shared layout (bytes):
//   ST4  float4[90*4]  ((u*9+vp-1)*4+kc) -> (Sp.re,Sp.im,Tm.re,Tm.im) : 0..5760
//   S0   float2[40]    (u*4+kc)                                       : 5760..6080
//   e4q  float4[90]                                                   : 6080..7520
//   e20p float4[90]                                                   : 7520..8960
//   zs   float2[715]                                                  : 8960..14680
//   union @14688:  A: Fs float2[200] / Ys float2[200]  (3200 B)
//                  B: Gre float[800] (3200) + Gim float[800] (3200)
#define SM_BYTES 21088

__global__ __launch_bounds__(256, 6) void k_main(const float* __restrict__ kern,
                                                 const float* __restrict__ bias,
                                                 float* __restrict__ out) {
    __shared__ __align__(16) char SM[SM_BYTES];
    float4* ST4_s  = (float4*)(SM);
    float2* S0_s   = (float2*)(SM + 5760);
    float4* e4q_s  = (float4*)(SM + 6080);
    float4* e20p_s = (float4*)(SM + 7520);
    float2* zs     = (float2*)(SM + 8960);
    float2* Fs     = (float2*)(SM + 14688);
    float2* Ys     = (float2*)(SM + 14688 + 1600);
    float*  Gre_s  = (float*)(SM + 14688);
    float*  Gim_s  = (float*)(SM + 14688 + 3200);

    int b = blockIdx.x, o = blockIdx.y;
    int tid = threadIdx.x;

    for (int t = tid; t < 200; t += 256) Fs[t] = FHAT_d[b * 200 + t];
    // Ys: conj(yhat)*SCALING computed in-CTA (replaces k_yhat kernel)
    {
        const float2* KFT = (const float2*)(TAB_d + OFF_KFT);
        const float SC = (float)(1.0 / sqrt(6.0 * 2.0 * 10000.0 / 900.0));
        for (int t = tid; t < 200; t += 256) {
            int i = t / 100, s = t % 100;
            float re = 0.f, im = 0.f;
            #pragma unroll
            for (int g = 0; g < 6; g++) {
                float kv = kern[(i * 5 + o) * 6 + g];
                float2 kf = KFT[s * 6 + g];
                re += kv * kf.x; im += kv * kf.y;
            }
            Ys[t] = make_float2(re * SC, -im * SC);
        }
    }
    {
        const float4* EQ = (const float4*)(TAB_d + OFF_E4Q);
        const float4* EP = (const float4*)(TAB_d + OFF_E20P);
        if (tid < 90) e4q_s[tid] = EQ[tid];
        else if (tid < 180) e20p_s[tid - 90] = EP[tid - 90];
    }
    __syncthreads();

    // ---- z-phase ----
    for (int t = tid; t < 715; t += 256) {
        int l = 0;
        #pragma unroll
        for (int j = 1; j < 10; j++) if (OFFU_c[j] <= t) l = j;
        int jj = t - OFFU_c[l]; int L = 2 * l + 1;
        int u = jj / L, vi = jj % L;
        int su = l * l + l + u, sv = l * l + vi;
        float2 f0 = Fs[su], f1 = Fs[100 + su], y0 = Ys[sv], y1 = Ys[100 + sv];
        float re = f0.x * y0.x - f0.y * y0.y + f1.x * y1.x - f1.y * y1.y;
        float im = f0.x * y0.y + f0.y * y0.x + f1.x * y1.y + f1.y * y1.x;
        zs[t] = make_float2(re, im);
    }
    __syncthreads();

    float bo = bias[o];
    ull bo2; PACK2(bo2, bo, bo);
    float* outp = out + ((size_t)(b * 5 + o)) * 8000;

    // S-phase lambda-style macro over chunk base k0 (KCH=4 slices)
    #define S_PHASE(K0)                                                          \
    for (int it = tid; it < 400; it += 256) {                                    \
        if (it < 40) {                                                           \
            int u = it / 4, kc = it % 4;                                         \
            const ull* D2 = (const ull*)(TAB_d + OFF_D2) + ((K0) + kc) * 715;    \
            ull acc = 0;                                                         \
            for (int l = u; l < 10; l++) {                                       \
                int idx = OFFU_c[l] + u * (2 * l + 1) + l;                       \
                ull z2 = *reinterpret_cast<const ull*>(&zs[idx]);                \
                FMA2(acc, D2[idx], z2, acc);                                     \
            }                                                                    \
            *reinterpret_cast<ull*>(&S0_s[u * 4 + kc]) = acc;                    \
        } else {                                                                 \
            int it2 = it - 40;                                                   \
            int u = it2 / 36, rem = it2 % 36;                                    \
            int vp = rem / 4 + 1, kc = rem % 4;                                  \
            int lmin = u > vp ? u : vp;                                          \
            const ull* D2 = (const ull*)(TAB_d + OFF_D2) + ((K0) + kc) * 715;    \
            ull accP = 0, accM = 0;                                              \
            for (int l = lmin; l < 10; l++) {                                    \
                int base = OFFU_c[l] + u * (2 * l + 1) + l;                      \
                ull zp = *reinterpret_cast<const ull*>(&zs[base + vp]);          \
                ull zm = *reinterpret_cast<const ull*>(&zs[base - vp]);          \
                FMA2(accP, D2[base + vp], zp, accP);                             \
                FMA2(accM, D2[base - vp], zm, accM);                             \
            }                                                                    \
            float pr, pi, mr, mi;                                                \
            UNPACK2(pr, pi, accP);                                               \
            UNPACK2(mr, mi, accM);                                               \
            ST4_s[(u * 9 + vp - 1) * 4 + kc] =                                   \
                make_float4(pr + mr, pi + mi, mi - pi, pr - mr);                 \
        }                                                                        \
    }

    S_PHASE(0)
    __syncthreads();

    for (int c = 0; c < 5; c++) {
        int k0 = c * KCH;
        // ---- G-phase: 200 threads, (q,u,khalf); each 2 kc slices ----
        if (tid < 200) {
            int kh = tid / 100, r = tid % 100;
            int q = r % 10, u = r / 10;
            int kc0 = kh * 2;
            ull acc_e[2], acc_o[2];
            #pragma unroll
            for (int j = 0; j < 2; j++) {
                acc_e[j] = *reinterpret_cast<const ull*>(&S0_s[u * 4 + kc0 + j]);
                acc_o[j] = 0ull;
            }
            const ulonglong2* STu = (const ulonglong2*)ST4_s;
            #pragma unroll
            for (int vp = 1; vp <= 9; vp++) {
                const ulonglong2 e2 =
                    *reinterpret_cast<const ulonglong2*>(&e4q_s[(vp - 1) * 10 + q]);
                int sbase = (u * 9 + vp - 1) * 4 + kc0;
                #pragma unroll
                for (int j = 0; j < 2; j++) {
                    ulonglong2 st = STu[sbase + j];
                    if (vp & 1) {
                        FMA2(acc_o[j], e2.x, st.x, acc_o[j]);
                        FMA2(acc_o[j], e2.y, st.y, acc_o[j]);
                    } else {
                        FMA2(acc_e[j], e2.x, st.x, acc_e[j]);
                        FMA2(acc_e[j], e2.y, st.y, acc_e[j]);
                    }
                }
            }
            #pragma unroll
            for (int j = 0; j < 2; j++) {
                int kc = kc0 + j;
                ull s, d;
                ADD2(s, acc_e[j], acc_o[j]);
                ull no = acc_o[j] ^ SIGN2;
                ADD2(d, acc_e[j], no);
                float gr, gi;
                UNPACK2(gr, gi, s);
                Gre_s[kc * 200 + u * 20 + q] = gr;
                Gim_s[kc * 200 + u * 20 + q] = gi;
                UNPACK2(gr, gi, d);
                Gre_s[kc * 200 + u * 20 + q + 10] = gr;
                Gim_s[kc * 200 + u * 20 + q + 10] = gi;
            }
        }
        __syncthreads();
        // ---- out-phase (200 threads) then S(c+1) (all threads), one barrier ----
        if (tid < 200) {
            int kh = tid / 100, r = tid % 100;
            int p = r / 10, qof = (r % 10) * 2;
            int kc0 = kh * 2;
            ull acc_e[2], acc_o[2];
            #pragma unroll
            for (int j = 0; j < 2; j++) {
                ull g0 = *reinterpret_cast<const ull*>(&Gre_s[(kc0 + j) * 200 + qof]);
                ADD2(acc_e[j], bo2, g0);
                acc_o[j] = 0ull;
            }
            #pragma unroll
            for (int uu = 1; uu <= 9; uu++) {
                const ulonglong2 e2 =
                    *reinterpret_cast<const ulonglong2*>(&e20p_s[p * 9 + uu - 1]);
                #pragma unroll
                for (int j = 0; j < 2; j++) {
                    int kc = kc0 + j;
                    ull gr = *reinterpret_cast<const ull*>(&Gre_s[kc * 200 + uu * 20 + qof]);
                    ull gi = *reinterpret_cast<const ull*>(&Gim_s[kc * 200 + uu * 20 + qof]);
                    if (uu & 1) {
                        FMA2(acc_o[j], e2.x, gr, acc_o[j]);
                        FMA2(acc_o[j], e2.y, gi, acc_o[j]);
                    } else {
                        FMA2(acc_e[j], e2.x, gr, acc_e[j]);
                        FMA2(acc_e[j], e2.y, gi, acc_e[j]);
                    }
                }
            }
            #pragma unroll
            for (int j = 0; j < 2; j++) {
                int kc = kc0 + j;
                ull s, d;
                ADD2(s, acc_e[j], acc_o[j]);
                ull no = acc_o[j] ^ SIGN2;
                ADD2(d, acc_e[j], no);
                *reinterpret_cast<ull*>(&outp[(k0 + kc) * 400 + p * 20 + qof]) = s;
                *reinterpret_cast<ull*>(&outp[(k0 + kc) * 400 + (p + 10) * 20 + qof]) = d;
            }
        }
        // S(c+1): writes ST4/S0 (not read by out-phase) — no barrier needed between
        if (c < 4) {
            S_PHASE(k0 + KCH)
        }
        __syncthreads();
    }
    #undef S_PHASE
}

// ================= launch ====================================================
extern "C" void kernel_launch(void* const* d_in, const int* in_sizes, int n_in,
                              void* d_out, int out_size) {
    const float* x    = (const float*)d_in[0];  // (512, 2, 60, 60)
    const float* kern = (const float*)d_in[1];  // (2, 5, 6)
    const float* bias = (const float*)d_in[2];  // (5)
    float* out = (float*)d_out;                 // (512, 5, 20, 20, 20)

    h_build_tables();
    cudaMemcpyToSymbolAsync(TAB_d, host_tab, sizeof(float) * TAB_LEN, 0,
                            cudaMemcpyHostToDevice, 0);

    k_fhat<<<1024, 128>>>(x);
    dim3 g(512, 5);
    k_main<<<g, 256>>>(kern, bias, out);
}

// round 9
// speedup vs baseline: 3.8891x; 1.2339x over previous
#include <cuda_runtime.h>
#include <math.h>
#include <string.h>

#define PI_D 3.141592653589793238462643383279502884

typedef unsigned long long ull;

// ---------------- packed table layout (floats) ----------------
// OFF_D    : D scalar [k][idx], 716-padded planes         : 20*716 = 14320
// OFF_W    : quadrature * wigner d_{m,0}, m>=0 packed     : 60*55  = 3300
// OFF_KFT  : kernel FT basis float2 [s][g]                : 1200
// OFF_E60  : float2 [a][m]                                : 1200
// OFF_E4Q  : float4 [vp-1][q] (ex,ex,ey,ey)               : 360
// OFF_E20P : float4 [p][uu-1] (2ex,2ex,-2ey,-2ey)         : 360
#define OFF_D    0
#define OFF_W    14320
#define OFF_KFT  17620
#define OFF_E60  18820
#define OFF_E4Q  20020
#define OFF_E20P 20380
#define TAB_LEN  20740

#define SIGN2 0x8000000080000000ULL

__device__ __align__(16) float TAB_d[TAB_LEN];
__device__ float2 FHAT_d[512 * 2 * 100];

// OFFU[l] = sum_{j<l} (j+1)(2j+1)  (u>=0 packed layout)
__constant__ int OFFU_c[11] = {0, 1, 7, 22, 50, 95, 161, 252, 372, 525, 715};
static const int OFFU_h[11] = {0, 1, 7, 22, 50, 95, 161, 252, 372, 525, 715};

// ---------------- packed f32x2 PTX helpers ----------------
#define FMA2(d, a, b, c) \
    asm("fma.rn.f32x2 %0, %1, %2, %3;" : "=l"(d) : "l"(a), "l"(b), "l"(c))
#define ADD2(d, a, b) \
    asm("add.rn.f32x2 %0, %1, %2;" : "=l"(d) : "l"(a), "l"(b))
#define PACK2(d, lo, hi) \
    asm("mov.b64 %0, {%1, %2};" : "=l"(d) : "r"(__float_as_uint(lo)), "r"(__float_as_uint(hi)))
#define UNPACK2(lo, hi, v) \
    do { unsigned _ulo, _uhi; \
         asm("mov.b64 {%0, %1}, %2;" : "=r"(_ulo), "=r"(_uhi) : "l"(v)); \
         lo = __uint_as_float(_ulo); hi = __uint_as_float(_uhi); } while (0)

// ================= HOST table generation (capture time only) =================
static double h_fact[19];

static double h_wig(int l, int mp, int m, double cb, double sb) {
    double pref = sqrt(h_fact[l + m] * h_fact[l - m] * h_fact[l + mp] * h_fact[l - mp]);
    int smin = (m - mp) > 0 ? (m - mp) : 0;
    int smax = (l + m) < (l - mp) ? (l + m) : (l - mp);
    double tot = 0.0;
    for (int s = smin; s <= smax; s++) {
        double den = h_fact[l + m - s] * h_fact[s] * h_fact[mp - m + s] * h_fact[l - mp - s];
        double t = pow(cb, (double)(2 * l + m - mp - 2 * s)) * pow(sb, (double)(mp - m + 2 * s)) / den;
        tot += ((mp - m + s) & 1) ? -t : t;
    }
    return pref * tot;
}

static float host_tab[TAB_LEN];

static void h_build_tables() {
    memset(host_tab, 0, sizeof(host_tab));
    h_fact[0] = 1.0;
    for (int j = 1; j < 19; j++) h_fact[j] = h_fact[j - 1] * (double)j;

    double wq[60];
    for (int j = 0; j < 60; j++) {
        double beta = PI_D * (2 * j + 1) / 120.0;
        double s = 0.0;
        for (int k = 0; k < 30; k++)
            s += sin((double)(2 * j + 1) * (2 * k + 1) * PI_D / 120.0) / (double)(2 * k + 1);
        wq[j] = (2.0 / 30.0) * sin(beta) * s;
    }

    // D scalar: [k][idx], plane stride 716 (idx 715 = zero pad)
    for (int k = 0; k < 20; k++) {
        double beta = PI_D * (2 * k + 1) / 40.0;
        double cb = cos(beta * 0.5), sb = sin(beta * 0.5);
        for (int l = 0; l < 10; l++) {
            int L = 2 * l + 1;
            for (int u = 0; u <= l; u++)
                for (int vi = 0; vi < L; vi++) {
                    int idx = OFFU_h[l] + u * L + vi;
                    host_tab[OFF_D + k * 716 + idx] =
                        (float)(h_wig(l, u, vi - l, cb, sb) * (double)L);
                }
        }
    }

    for (int k = 0; k < 60; k++) {
        double beta = PI_D * (2 * k + 1) / 120.0;
        double cb = cos(beta * 0.5), sb = sin(beta * 0.5);
        for (int l = 0; l < 10; l++)
            for (int m = 0; m <= l; m++)
                host_tab[OFF_W + k * 55 + l * (l + 1) / 2 + m] =
                    (float)(wq[k] * h_wig(l, m, 0, cb, sb));
    }

    {
        double beta = PI_D / 160.0;
        double cb = cos(beta * 0.5), sb = sin(beta * 0.5);
        for (int l = 0; l < 10; l++)
            for (int m = -l; m <= l; m++) {
                int s = l * l + l + m;
                double d0 = h_wig(l, m, 0, cb, sb);
                for (int g = 0; g < 6; g++) {
                    double ga = 2.0 * PI_D * (double)g / 6.0;
                    host_tab[OFF_KFT + (s * 6 + g) * 2 + 0] = (float)(d0 * cos((double)m * ga));
                    host_tab[OFF_KFT + (s * 6 + g) * 2 + 1] = (float)(-d0 * sin((double)m * ga));
                }
            }
    }

    for (int a = 0; a < 60; a++)
        for (int m = 0; m < 10; m++) {
            double th = -2.0 * PI_D * (double)a * (double)m / 60.0;
            host_tab[OFF_E60 + (a * 10 + m) * 2 + 0] = (float)cos(th);
            host_tab[OFF_E60 + (a * 10 + m) * 2 + 1] = (float)sin(th);
        }

    for (int vp = 1; vp <= 9; vp++)
        for (int q = 0; q < 10; q++) {
            double th = 2.0 * PI_D * (double)q * (double)vp / 20.0;
            float ex = (float)cos(th), ey = (float)sin(th);
            int base = OFF_E4Q + ((vp - 1) * 10 + q) * 4;
            host_tab[base + 0] = ex; host_tab[base + 1] = ex;
            host_tab[base + 2] = ey; host_tab[base + 3] = ey;
        }

    for (int p = 0; p < 10; p++)
        for (int uu = 1; uu <= 9; uu++) {
            double th = 2.0 * PI_D * (double)p * (double)uu / 20.0;
            float ex = (float)(2.0 * cos(th)), ey = (float)(2.0 * sin(th));
            int base = OFF_E20P + (p * 9 + uu - 1) * 4;
            host_tab[base + 0] = ex;  host_tab[base + 1] = ex;
            host_tab[base + 2] = -ey; host_tab[base + 3] = -ey;
        }
}

// ================= stage 1: fhat[b][i][s] ====================================
__global__ __launch_bounds__(128) void k_fhat(const float* __restrict__ x) {
    __shared__ __align__(16) float  xsT[60 * 61];  // [a][k], pitch 61
    __shared__ __align__(16) float2 xf2[600];      // [k][m]
    __shared__ __align__(16) float2 e60[600];      // [a][m]
    int bi = blockIdx.x;   // b*2 + i
    const float* xp = x + (size_t)bi * 3600;
    const float2* E60g = (const float2*)(TAB_d + OFF_E60);
    for (int t = threadIdx.x; t < 3600; t += 128) {
        int k = t / 60, a = t % 60;
        xsT[a * 61 + k] = xp[t];
    }
    for (int t = threadIdx.x; t < 600; t += 128) e60[t] = E60g[t];
    __syncthreads();
    for (int t = threadIdx.x; t < 300; t += 128) {
        int mp = t / 60, k = t % 60;
        ull acc0 = 0, acc1 = 0;
        #pragma unroll 4
        for (int a = 0; a < 60; a++) {
            float xv = xsT[a * 61 + k];
            ull xv2; PACK2(xv2, xv, xv);
            const ulonglong2 e2 = *reinterpret_cast<const ulonglong2*>(&e60[a * 10 + 2 * mp]);
            FMA2(acc0, xv2, e2.x, acc0);
            FMA2(acc1, xv2, e2.y, acc1);
        }
        float r0, i0, r1, i1;
        UNPACK2(r0, i0, acc0);
        UNPACK2(r1, i1, acc1);
        xf2[k * 10 + 2 * mp]     = make_float2(r0, i0);
        xf2[k * 10 + 2 * mp + 1] = make_float2(r1, i1);
    }
    __syncthreads();
    // final contraction: 110 threads (sp x half), shfl-pair reduce
    {
        int t = threadIdx.x;
        int sp = t >> 1;
        if (sp > 54) sp = 54;
        int half = t & 1;
        int l = 0;
        #pragma unroll
        for (int j = 1; j < 10; j++) if (j * (j + 1) / 2 <= sp) l = j;
        int m = sp - l * (l + 1) / 2;
        float re = 0.f, im = 0.f;
        int k0 = half * 30;
        #pragma unroll 5
        for (int k = k0; k < k0 + 30; k++) {
            float w = TAB_d[OFF_W + k * 55 + sp];
            float2 v = xf2[k * 10 + m];
            re += w * v.x; im += w * v.y;
        }
        re += __shfl_xor_sync(0xFFFFFFFFu, re, 1);
        im += __shfl_xor_sync(0xFFFFFFFFu, im, 1);
        if (half == 0 && t < 110) {
            FHAT_d[bi * 100 + l * l + l + m] = make_float2(re, im);
            if (m > 0) {
                float sg = (m & 1) ? -1.f : 1.f;
                FHAT_d[bi * 100 + l * l + l - m] = make_float2(sg * re, -sg * im);
            }
        }
    }
}

// ================= stage 3: main — D staged through smem =====================
#define KCH 4   // 5 chunks of 4 k's

// shared layout (bytes):
//   Dbuf float[716*4]                                 : 0     .. 11456
//   ST4  float4[360] ((u*9+vp-1)*4+kc)                : 11456 .. 17216
//   S0   float2[40]  (u*4+kc)                         : 17216 .. 17536
//   e4q  float4[90]                                   : 17536 .. 18976
//   e20p float4[90]                                   : 18976 .. 20416
//   zs   float2[715]                                  : 20416 .. 26136 (pad 26144)
//   union @26144: A: Fs float2[200], Ys float2[200] @27744
//                 B: Gre float[800] @26144, Gim float[800] @29344
#define SM_BYTES 32544

__global__ __launch_bounds__(256, 6) void k_main(const float* __restrict__ kern,
                                                 const float* __restrict__ bias,
                                                 float* __restrict__ out) {
    __shared__ __align__(16) char SM[SM_BYTES];
    float*  Dbuf_s = (float*)(SM);
    float4* ST4_s  = (float4*)(SM + 11456);
    float2* S0_s   = (float2*)(SM + 17216);
    float4* e4q_s  = (float4*)(SM + 17536);
    float4* e20p_s = (float4*)(SM + 18976);
    float2* zs     = (float2*)(SM + 20416);
    float2* Fs     = (float2*)(SM + 26144);
    float2* Ys     = (float2*)(SM + 27744);
    float*  Gre_s  = (float*)(SM + 26144);
    float*  Gim_s  = (float*)(SM + 29344);

    int b = blockIdx.x, o = blockIdx.y;
    int tid = threadIdx.x;

    // D chunk copy: 716 float4 = 4 planes of 179 float4 (716-pad floats each)
    #define D_LOAD(K0, T0, NT)                                                   \
    {   const float4* Dg = (const float4*)(TAB_d + OFF_D) + (K0) * 179;          \
        float4* Db = (float4*)Dbuf_s;                                            \
        for (int t = (T0); t < 716; t += (NT)) Db[t] = Dg[t];                    \
    }

    // ---- initial loads (+ D chunk 0) ----
    for (int t = tid; t < 200; t += 256) Fs[t] = FHAT_d[b * 200 + t];
    {
        const float2* KFT = (const float2*)(TAB_d + OFF_KFT);
        const float SC = (float)(1.0 / sqrt(6.0 * 2.0 * 10000.0 / 900.0));
        for (int t = tid; t < 200; t += 256) {
            int i = t / 100, s = t % 100;
            float re = 0.f, im = 0.f;
            #pragma unroll
            for (int g = 0; g < 6; g++) {
                float kv = kern[(i * 5 + o) * 6 + g];
                float2 kf = KFT[s * 6 + g];
                re += kv * kf.x; im += kv * kf.y;
            }
            Ys[t] = make_float2(re * SC, -im * SC);
        }
    }
    {
        const float4* EQ = (const float4*)(TAB_d + OFF_E4Q);
        const float4* EP = (const float4*)(TAB_d + OFF_E20P);
        if (tid < 90) e4q_s[tid] = EQ[tid];
        else if (tid < 180) e20p_s[tid - 90] = EP[tid - 90];
    }
    D_LOAD(0, tid, 256)
    __syncthreads();

    // ---- z-phase ----
    for (int t = tid; t < 715; t += 256) {
        int l = 0;
        #pragma unroll
        for (int j = 1; j < 10; j++) if (OFFU_c[j] <= t) l = j;
        int jj = t - OFFU_c[l]; int L = 2 * l + 1;
        int u = jj / L, vi = jj % L;
        int su = l * l + l + u, sv = l * l + vi;
        float2 f0 = Fs[su], f1 = Fs[100 + su], y0 = Ys[sv], y1 = Ys[100 + sv];
        float re = f0.x * y0.x - f0.y * y0.y + f1.x * y1.x - f1.y * y1.y;
        float im = f0.x * y0.y + f0.y * y0.x + f1.x * y1.y + f1.y * y1.x;
        zs[t] = make_float2(re, im);
    }
    __syncthreads();

    float bo = bias[o];
    ull bo2; PACK2(bo2, bo, bo);
    float* outp = out + ((size_t)(b * 5 + o)) * 8000;

    // S-phase over chunk in Dbuf (KCH=4 slices)
    #define S_PHASE()                                                            \
    for (int it = tid; it < 400; it += 256) {                                    \
        if (it < 40) {                                                           \
            int u = it / 4, kc = it % 4;                                         \
            const float* Dk = Dbuf_s + kc * 716;                                 \
            ull acc = 0;                                                         \
            for (int l = u; l < 10; l++) {                                       \
                int idx = OFFU_c[l] + u * (2 * l + 1) + l;                       \
                float d = Dk[idx];                                               \
                ull d2; PACK2(d2, d, d);                                         \
                ull z2 = *reinterpret_cast<const ull*>(&zs[idx]);                \
                FMA2(acc, d2, z2, acc);                                          \
            }                                                                    \
            *reinterpret_cast<ull*>(&S0_s[u * 4 + kc]) = acc;                    \
        } else {                                                                 \
            int it2 = it - 40;                                                   \
            int u = it2 / 36, rem = it2 % 36;                                    \
            int vp = rem / 4 + 1, kc = rem % 4;                                  \
            int lmin = u > vp ? u : vp;                                          \
            const float* Dk = Dbuf_s + kc * 716;                                 \
            ull accP = 0, accM = 0;                                              \
            for (int l = lmin; l < 10; l++) {                                    \
                int base = OFFU_c[l] + u * (2 * l + 1) + l;                      \
                float dp = Dk[base + vp], dm = Dk[base - vp];                    \
                ull dp2, dm2; PACK2(dp2, dp, dp); PACK2(dm2, dm, dm);            \
                ull zp = *reinterpret_cast<const ull*>(&zs[base + vp]);          \
                ull zm = *reinterpret_cast<const ull*>(&zs[base - vp]);          \
                FMA2(accP, dp2, zp, accP);                                       \
                FMA2(accM, dm2, zm, accM);                                       \
            }                                                                    \
            float pr, pi, mr, mi;                                                \
            UNPACK2(pr, pi, accP);                                               \
            UNPACK2(mr, mi, accM);                                               \
            ST4_s[(u * 9 + vp - 1) * 4 + kc] =                                   \
                make_float4(pr + mr, pi + mi, mi - pi, pr - mr);                 \
        }                                                                        \
    }

    S_PHASE()
    __syncthreads();

    for (int c = 0; c < 5; c++) {
        int k0 = c * KCH;
        // ---- G-phase (threads <200) || D-load chunk c+1 (threads >=200) ----
        if (tid < 200) {
            int kh = tid / 100, r = tid % 100;
            int q = r % 10, u = r / 10;
            int kc0 = kh * 2;
            ull acc_e[2], acc_o[2];
            #pragma unroll
            for (int j = 0; j < 2; j++) {
                acc_e[j] = *reinterpret_cast<const ull*>(&S0_s[u * 4 + kc0 + j]);
                acc_o[j] = 0ull;
            }
            const ulonglong2* STu = (const ulonglong2*)ST4_s;
            #pragma unroll
            for (int vp = 1; vp <= 9; vp++) {
                const ulonglong2 e2 =
                    *reinterpret_cast<const ulonglong2*>(&e4q_s[(vp - 1) * 10 + q]);
                int sbase = (u * 9 + vp - 1) * 4 + kc0;
                #pragma unroll
                for (int j = 0; j < 2; j++) {
                    ulonglong2 st = STu[sbase + j];
                    if (vp & 1) {
                        FMA2(acc_o[j], e2.x, st.x, acc_o[j]);
                        FMA2(acc_o[j], e2.y, st.y, acc_o[j]);
                    } else {
                        FMA2(acc_e[j], e2.x, st.x, acc_e[j]);
                        FMA2(acc_e[j], e2.y, st.y, acc_e[j]);
                    }
                }
            }
            #pragma unroll
            for (int j = 0; j < 2; j++) {
                int kc = kc0 + j;
                ull s, d;
                ADD2(s, acc_e[j], acc_o[j]);
                ull no = acc_o[j] ^ SIGN2;
                ADD2(d, acc_e[j], no);
                float gr, gi;
                UNPACK2(gr, gi, s);
                Gre_s[kc * 200 + u * 20 + q] = gr;
                Gim_s[kc * 200 + u * 20 + q] = gi;
                UNPACK2(gr, gi, d);
                Gre_s[kc * 200 + u * 20 + q + 10] = gr;
                Gim_s[kc * 200 + u * 20 + q + 10] = gi;
            }
        } else if (c < 4) {
            D_LOAD(k0 + KCH, tid - 200, 56)
        }
        __syncthreads();
        // ---- out-phase (threads <200) then S(c+1) (all threads) ----
        if (tid < 200) {
            int kh = tid / 100, r = tid % 100;
            int p = r / 10, qof = (r % 10) * 2;
            int kc0 = kh * 2;
            ull acc_e[2], acc_o[2];
            #pragma unroll
            for (int j = 0; j < 2; j++) {
                ull g0 = *reinterpret_cast<const ull*>(&Gre_s[(kc0 + j) * 200 + qof]);
                ADD2(acc_e[j], bo2, g0);
                acc_o[j] = 0ull;
            }
            #pragma unroll
            for (int uu = 1; uu <= 9; uu++) {
                const ulonglong2 e2 =
                    *reinterpret_cast<const ulonglong2*>(&e20p_s[p * 9 + uu - 1]);
                #pragma unroll
                for (int j = 0; j < 2; j++) {
                    int kc = kc0 + j;
                    ull gr = *reinterpret_cast<const ull*>(&Gre_s[kc * 200 + uu * 20 + qof]);
                    ull gi = *reinterpret_cast<const ull*>(&Gim_s[kc * 200 + uu * 20 + qof]);
                    if (uu & 1) {
                        FMA2(acc_o[j], e2.x, gr, acc_o[j]);
                        FMA2(acc_o[j], e2.y, gi, acc_o[j]);
                    } else {
                        FMA2(acc_e[j], e2.x, gr, acc_e[j]);
                        FMA2(acc_e[j], e2.y, gi, acc_e[j]);
                    }
                }
            }
            #pragma unroll
            for (int j = 0; j < 2; j++) {
                int kc = kc0 + j;
                ull s, d;
                ADD2(s, acc_e[j], acc_o[j]);
                ull no = acc_o[j] ^ SIGN2;
                ADD2(d, acc_e[j], no);
                *reinterpret_cast<ull*>(&outp[(k0 + kc) * 400 + p * 20 + qof]) = s;
                *reinterpret_cast<ull*>(&outp[(k0 + kc) * 400 + (p + 10) * 20 + qof]) = d;
            }
        }
        // S(c+1): reads Dbuf (filled during G-phase, barrier above) + zs
        if (c < 4) {
            S_PHASE()
        }
        __syncthreads();
    }
    #undef S_PHASE
    #undef D_LOAD
}

// ================= launch ====================================================
extern "C" void kernel_launch(void* const* d_in, const int* in_sizes, int n_in,
                              void* d_out, int out_size) {
    const float* x    = (const float*)d_in[0];  // (512, 2, 60, 60)
    const float* kern = (const float*)d_in[1];  // (2, 5, 6)
    const float* bias = (const float*)d_in[2];  // (5)
    float* out = (float*)d_out;                 // (512, 5, 20, 20, 20)

    h_build_tables();
    cudaMemcpyToSymbolAsync(TAB_d, host_tab, sizeof(float) * TAB_LEN, 0,
                            cudaMemcpyHostToDevice, 0);

    k_fhat<<<1024, 128>>>(x);
    dim3 g(512, 5);
    k_main<<<g, 256>>>(kern, bias, out);
}

// round 11
// speedup vs baseline: 3.9134x; 1.0063x over previous
#include <cuda_runtime.h>
#include <math.h>
#include <string.h>

#define PI_D 3.141592653589793238462643383279502884

typedef unsigned long long ull;

// ---------------- packed table layout (floats) ----------------
// OFF_D    : D interleaved [chunk5][idx716][kc4]          : 14320
// OFF_W    : quadrature * wigner d_{m,0}, m>=0 packed     : 3300
// OFF_KFT  : kernel FT basis float2 [s][g]                : 1200
// OFF_E60  : float2 [a][m]                                : 1200
// OFF_E4Q  : float4 [vp-1][q] (ex,ex,ey,ey)               : 360
// OFF_E20P : float4 [p][uu-1] (2ex,2ex,-2ey,-2ey)         : 360
#define OFF_D    0
#define OFF_W    14320
#define OFF_KFT  17620
#define OFF_E60  18820
#define OFF_E4Q  20020
#define OFF_E20P 20380
#define TAB_LEN  20740

#define SIGN2 0x8000000080000000ULL

__device__ __align__(16) float TAB_d[TAB_LEN];
__device__ float2 FHAT_d[512 * 2 * 100];

// OFFU[l] = sum_{j<l} (j+1)(2j+1)  (u>=0 packed layout)
__constant__ int OFFU_c[11] = {0, 1, 7, 22, 50, 95, 161, 252, 372, 525, 715};
static const int OFFU_h[11] = {0, 1, 7, 22, 50, 95, 161, 252, 372, 525, 715};

// ---------------- packed f32x2 PTX helpers ----------------
#define FMA2(d, a, b, c) \
    asm("fma.rn.f32x2 %0, %1, %2, %3;" : "=l"(d) : "l"(a), "l"(b), "l"(c))
#define ADD2(d, a, b) \
    asm("add.rn.f32x2 %0, %1, %2;" : "=l"(d) : "l"(a), "l"(b))
#define PACK2(d, lo, hi) \
    asm("mov.b64 %0, {%1, %2};" : "=l"(d) : "r"(__float_as_uint(lo)), "r"(__float_as_uint(hi)))
#define UNPACK2(lo, hi, v) \
    do { unsigned _ulo, _uhi; \
         asm("mov.b64 {%0, %1}, %2;" : "=r"(_ulo), "=r"(_uhi) : "l"(v)); \
         lo = __uint_as_float(_ulo); hi = __uint_as_float(_uhi); } while (0)

// ================= HOST table generation (capture time only) =================
static double h_fact[19];

static double h_wig(int l, int mp, int m, double cb, double sb) {
    double pref = sqrt(h_fact[l + m] * h_fact[l - m] * h_fact[l + mp] * h_fact[l - mp]);
    int smin = (m - mp) > 0 ? (m - mp) : 0;
    int smax = (l + m) < (l - mp) ? (l + m) : (l - mp);
    double tot = 0.0;
    for (int s = smin; s <= smax; s++) {
        double den = h_fact[l + m - s] * h_fact[s] * h_fact[mp - m + s] * h_fact[l - mp - s];
        double t = pow(cb, (double)(2 * l + m - mp - 2 * s)) * pow(sb, (double)(mp - m + 2 * s)) / den;
        tot += ((mp - m + s) & 1) ? -t : t;
    }
    return pref * tot;
}

static float host_tab[TAB_LEN];

static void h_build_tables() {
    memset(host_tab, 0, sizeof(host_tab));
    h_fact[0] = 1.0;
    for (int j = 1; j < 19; j++) h_fact[j] = h_fact[j - 1] * (double)j;

    double wq[60];
    for (int j = 0; j < 60; j++) {
        double beta = PI_D * (2 * j + 1) / 120.0;
        double s = 0.0;
        for (int k = 0; k < 30; k++)
            s += sin((double)(2 * j + 1) * (2 * k + 1) * PI_D / 120.0) / (double)(2 * k + 1);
        wq[j] = (2.0 / 30.0) * sin(beta) * s;
    }

    // D interleaved: [chunk][idx][kc], k = chunk*4 + kc
    for (int k = 0; k < 20; k++) {
        int c = k / 4, kc = k % 4;
        double beta = PI_D * (2 * k + 1) / 40.0;
        double cb = cos(beta * 0.5), sb = sin(beta * 0.5);
        for (int l = 0; l < 10; l++) {
            int L = 2 * l + 1;
            for (int u = 0; u <= l; u++)
                for (int vi = 0; vi < L; vi++) {
                    int idx = OFFU_h[l] + u * L + vi;
                    host_tab[OFF_D + c * 2864 + idx * 4 + kc] =
                        (float)(h_wig(l, u, vi - l, cb, sb) * (double)L);
                }
        }
    }

    for (int k = 0; k < 60; k++) {
        double beta = PI_D * (2 * k + 1) / 120.0;
        double cb = cos(beta * 0.5), sb = sin(beta * 0.5);
        for (int l = 0; l < 10; l++)
            for (int m = 0; m <= l; m++)
                host_tab[OFF_W + k * 55 + l * (l + 1) / 2 + m] =
                    (float)(wq[k] * h_wig(l, m, 0, cb, sb));
    }

    {
        double beta = PI_D / 160.0;
        double cb = cos(beta * 0.5), sb = sin(beta * 0.5);
        for (int l = 0; l < 10; l++)
            for (int m = -l; m <= l; m++) {
                int s = l * l + l + m;
                double d0 = h_wig(l, m, 0, cb, sb);
                for (int g = 0; g < 6; g++) {
                    double ga = 2.0 * PI_D * (double)g / 6.0;
                    host_tab[OFF_KFT + (s * 6 + g) * 2 + 0] = (float)(d0 * cos((double)m * ga));
                    host_tab[OFF_KFT + (s * 6 + g) * 2 + 1] = (float)(-d0 * sin((double)m * ga));
                }
            }
    }

    for (int a = 0; a < 60; a++)
        for (int m = 0; m < 10; m++) {
            double th = -2.0 * PI_D * (double)a * (double)m / 60.0;
            host_tab[OFF_E60 + (a * 10 + m) * 2 + 0] = (float)cos(th);
            host_tab[OFF_E60 + (a * 10 + m) * 2 + 1] = (float)sin(th);
        }

    for (int vp = 1; vp <= 9; vp++)
        for (int q = 0; q < 10; q++) {
            double th = 2.0 * PI_D * (double)q * (double)vp / 20.0;
            float ex = (float)cos(th), ey = (float)sin(th);
            int base = OFF_E4Q + ((vp - 1) * 10 + q) * 4;
            host_tab[base + 0] = ex; host_tab[base + 1] = ex;
            host_tab[base + 2] = ey; host_tab[base + 3] = ey;
        }

    for (int p = 0; p < 10; p++)
        for (int uu = 1; uu <= 9; uu++) {
            double th = 2.0 * PI_D * (double)p * (double)uu / 20.0;
            float ex = (float)(2.0 * cos(th)), ey = (float)(2.0 * sin(th));
            int base = OFF_E20P + (p * 9 + uu - 1) * 4;
            host_tab[base + 0] = ex;  host_tab[base + 1] = ex;
            host_tab[base + 2] = -ey; host_tab[base + 3] = -ey;
        }
}

// ================= stage 1: fhat[b][i][s] ====================================
__global__ __launch_bounds__(128) void k_fhat(const float* __restrict__ x) {
    __shared__ __align__(16) float  xsT[60 * 61];  // [a][k], pitch 61
    __shared__ __align__(16) float2 xf2[600];      // [k][m]
    __shared__ __align__(16) float2 e60[600];      // [a][m]
    int bi = blockIdx.x;   // b*2 + i
    const float* xp = x + (size_t)bi * 3600;
    const float2* E60g = (const float2*)(TAB_d + OFF_E60);
    for (int t = threadIdx.x; t < 3600; t += 128) {
        int k = t / 60, a = t % 60;
        xsT[a * 61 + k] = xp[t];
    }
    for (int t = threadIdx.x; t < 600; t += 128) e60[t] = E60g[t];
    __syncthreads();
    for (int t = threadIdx.x; t < 300; t += 128) {
        int mp = t / 60, k = t % 60;
        ull acc0 = 0, acc1 = 0;
        #pragma unroll 4
        for (int a = 0; a < 60; a++) {
            float xv = xsT[a * 61 + k];
            ull xv2; PACK2(xv2, xv, xv);
            const ulonglong2 e2 = *reinterpret_cast<const ulonglong2*>(&e60[a * 10 + 2 * mp]);
            FMA2(acc0, xv2, e2.x, acc0);
            FMA2(acc1, xv2, e2.y, acc1);
        }
        float r0, i0, r1, i1;
        UNPACK2(r0, i0, acc0);
        UNPACK2(r1, i1, acc1);
        xf2[k * 10 + 2 * mp]     = make_float2(r0, i0);
        xf2[k * 10 + 2 * mp + 1] = make_float2(r1, i1);
    }
    __syncthreads();
    {
        int t = threadIdx.x;
        int sp = t >> 1;
        if (sp > 54) sp = 54;
        int half = t & 1;
        int l = 0;
        #pragma unroll
        for (int j = 1; j < 10; j++) if (j * (j + 1) / 2 <= sp) l = j;
        int m = sp - l * (l + 1) / 2;
        float re = 0.f, im = 0.f;
        int k0 = half * 30;
        #pragma unroll 5
        for (int k = k0; k < k0 + 30; k++) {
            float w = TAB_d[OFF_W + k * 55 + sp];
            float2 v = xf2[k * 10 + m];
            re += w * v.x; im += w * v.y;
        }
        re += __shfl_xor_sync(0xFFFFFFFFu, re, 1);
        im += __shfl_xor_sync(0xFFFFFFFFu, im, 1);
        if (half == 0 && t < 110) {
            FHAT_d[bi * 100 + l * l + l + m] = make_float2(re, im);
            if (m > 0) {
                float sg = (m & 1) ? -1.f : 1.f;
                FHAT_d[bi * 100 + l * l + l - m] = make_float2(sg * re, -sg * im);
            }
        }
    }
}

// ================= stage 3: main — kc-interleaved D, vp-major ST =============
#define KCH 4   // 5 chunks of 4 k's

// shared layout (bytes):
//   Dbuf float[716*4] interleaved [idx][kc]           : 0     .. 11456
//   ST4  float4[360]  [(vp-1)*40 + u*4 + kc]          : 11456 .. 17216
//   S0   float2[40]   (u*4+kc)                        : 17216 .. 17536
//   e4q  float4[90]                                   : 17536 .. 18976
//   e20p float4[90]                                   : 18976 .. 20416
//   zs   float2[715]                                  : 20416 .. 26136 (pad 26144)
//   union @26144: A: Fs float2[200], Ys float2[200] @27744
//                 B: Gre float[800] @26144, Gim float[800] @29344
#define SM_BYTES 32544

__global__ __launch_bounds__(256, 6) void k_main(const float* __restrict__ kern,
                                                 const float* __restrict__ bias,
                                                 float* __restrict__ out) {
    __shared__ __align__(16) char SM[SM_BYTES];
    float*  Dbuf_s = (float*)(SM);
    float4* ST4_s  = (float4*)(SM + 11456);
    float2* S0_s   = (float2*)(SM + 17216);
    float4* e4q_s  = (float4*)(SM + 17536);
    float4* e20p_s = (float4*)(SM + 18976);
    float2* zs     = (float2*)(SM + 20416);
    float2* Fs     = (float2*)(SM + 26144);
    float2* Ys     = (float2*)(SM + 27744);
    float*  Gre_s  = (float*)(SM + 26144);
    float*  Gim_s  = (float*)(SM + 29344);

    int b = blockIdx.x, o = blockIdx.y;
    int tid = threadIdx.x;

    // D chunk copy: chunk C -> 716 float4 ([idx][kc] interleaved)
    #define D_LOAD(C, T0, NT)                                                    \
    {   const float4* Dg = (const float4*)(TAB_d + OFF_D) + (C) * 716;           \
        float4* Db = (float4*)Dbuf_s;                                            \
        for (int t = (T0); t < 716; t += (NT)) Db[t] = Dg[t];                    \
    }

    // ---- initial loads (+ D chunk 0) ----
    for (int t = tid; t < 200; t += 256) Fs[t] = FHAT_d[b * 200 + t];
    {
        const float2* KFT = (const float2*)(TAB_d + OFF_KFT);
        const float SC = (float)(1.0 / sqrt(6.0 * 2.0 * 10000.0 / 900.0));
        for (int t = tid; t < 200; t += 256) {
            int i = t / 100, s = t % 100;
            float re = 0.f, im = 0.f;
            #pragma unroll
            for (int g = 0; g < 6; g++) {
                float kv = kern[(i * 5 + o) * 6 + g];
                float2 kf = KFT[s * 6 + g];
                re += kv * kf.x; im += kv * kf.y;
            }
            Ys[t] = make_float2(re * SC, -im * SC);
        }
    }
    {
        const float4* EQ = (const float4*)(TAB_d + OFF_E4Q);
        const float4* EP = (const float4*)(TAB_d + OFF_E20P);
        if (tid < 90) e4q_s[tid] = EQ[tid];
        else if (tid < 180) e20p_s[tid - 90] = EP[tid - 90];
    }
    D_LOAD(0, tid, 256)
    __syncthreads();

    // ---- z-phase ----
    for (int t = tid; t < 715; t += 256) {
        int l = 0;
        #pragma unroll
        for (int j = 1; j < 10; j++) if (OFFU_c[j] <= t) l = j;
        int jj = t - OFFU_c[l]; int L = 2 * l + 1;
        int u = jj / L, vi = jj % L;
        int su = l * l + l + u, sv = l * l + vi;
        float2 f0 = Fs[su], f1 = Fs[100 + su], y0 = Ys[sv], y1 = Ys[100 + sv];
        float re = f0.x * y0.x - f0.y * y0.y + f1.x * y1.x - f1.y * y1.y;
        float im = f0.x * y0.y + f0.y * y0.x + f1.x * y1.y + f1.y * y1.x;
        zs[t] = make_float2(re, im);
    }
    __syncthreads();

    float bo = bias[o];
    ull bo2; PACK2(bo2, bo, bo);
    float* outp = out + ((size_t)(b * 5 + o)) * 8000;

    // S-phase over chunk in Dbuf (interleaved [idx][kc]); ST layout [vp][u][kc]
    #define S_PHASE()                                                            \
    for (int it = tid; it < 400; it += 256) {                                    \
        if (it < 40) {                                                           \
            int u = it / 4, kc = it % 4;                                         \
            ull acc = 0;                                                         \
            for (int l = u; l < 10; l++) {                                       \
                int idx = OFFU_c[l] + u * (2 * l + 1) + l;                       \
                float d = Dbuf_s[idx * 4 + kc];                                  \
                ull d2; PACK2(d2, d, d);                                         \
                ull z2 = *reinterpret_cast<const ull*>(&zs[idx]);                \
                FMA2(acc, d2, z2, acc);                                          \
            }                                                                    \
            *reinterpret_cast<ull*>(&S0_s[u * 4 + kc]) = acc;                    \
        } else {                                                                 \
            int it2 = it - 40;                                                   \
            int u = it2 / 36, rem = it2 % 36;                                    \
            int vp = rem / 4 + 1, kc = rem % 4;                                  \
            int lmin = u > vp ? u : vp;                                          \
            ull accP = 0, accM = 0;                                              \
            for (int l = lmin; l < 10; l++) {                                    \
                int base = OFFU_c[l] + u * (2 * l + 1) + l;                      \
                float dp = Dbuf_s[(base + vp) * 4 + kc];                         \
                float dm = Dbuf_s[(base - vp) * 4 + kc];                         \
                ull dp2, dm2; PACK2(dp2, dp, dp); PACK2(dm2, dm, dm);            \
                ull zp = *reinterpret_cast<const ull*>(&zs[base + vp]);          \
                ull zm = *reinterpret_cast<const ull*>(&zs[base - vp]);          \
                FMA2(accP, dp2, zp, accP);                                       \
                FMA2(accM, dm2, zm, accM);                                       \
            }                                                                    \
            float pr, pi, mr, mi;                                                \
            UNPACK2(pr, pi, accP);                                               \
            UNPACK2(mr, mi, accM);                                               \
            ST4_s[(vp - 1) * 40 + u * 4 + kc] =                                  \
                make_float4(pr + mr, pi + mi, mi - pi, pr - mr);                 \
        }                                                                        \
    }

    S_PHASE()
    __syncthreads();

    for (int c = 0; c < 5; c++) {
        int k0 = c * KCH;
        // ---- G-phase (threads <200) || D-load chunk c+1 (threads >=200) ----
        if (tid < 200) {
            int kh = tid / 100, r = tid % 100;
            int q = r % 10, u = r / 10;
            int kc0 = kh * 2;
            ull acc_e[2], acc_o[2];
            #pragma unroll
            for (int j = 0; j < 2; j++) {
                acc_e[j] = *reinterpret_cast<const ull*>(&S0_s[u * 4 + kc0 + j]);
                acc_o[j] = 0ull;
            }
            const ulonglong2* STu = (const ulonglong2*)ST4_s;
            #pragma unroll
            for (int vp = 1; vp <= 9; vp++) {
                const ulonglong2 e2 =
                    *reinterpret_cast<const ulonglong2*>(&e4q_s[(vp - 1) * 10 + q]);
                int sbase = (vp - 1) * 40 + u * 4 + kc0;
                #pragma unroll
                for (int j = 0; j < 2; j++) {
                    ulonglong2 st = STu[sbase + j];
                    if (vp & 1) {
                        FMA2(acc_o[j], e2.x, st.x, acc_o[j]);
                        FMA2(acc_o[j], e2.y, st.y, acc_o[j]);
                    } else {
                        FMA2(acc_e[j], e2.x, st.x, acc_e[j]);
                        FMA2(acc_e[j], e2.y, st.y, acc_e[j]);
                    }
                }
            }
            #pragma unroll
            for (int j = 0; j < 2; j++) {
                int kc = kc0 + j;
                ull s, d;
                ADD2(s, acc_e[j], acc_o[j]);
                ull no = acc_o[j] ^ SIGN2;
                ADD2(d, acc_e[j], no);
                float gr, gi;
                UNPACK2(gr, gi, s);
                Gre_s[kc * 200 + u * 20 + q] = gr;
                Gim_s[kc * 200 + u * 20 + q] = gi;
                UNPACK2(gr, gi, d);
                Gre_s[kc * 200 + u * 20 + q + 10] = gr;
                Gim_s[kc * 200 + u * 20 + q + 10] = gi;
            }
        } else if (c < 4) {
            D_LOAD(c + 1, tid - 200, 56)
        }
        __syncthreads();
        // ---- out-phase (threads <200) then S(c+1) (all threads) ----
        if (tid < 200) {
            int kh = tid / 100, r = tid % 100;
            int p = r / 10, qof = (r % 10) * 2;
            int kc0 = kh * 2;
            ull acc_e[2], acc_o[2];
            #pragma unroll
            for (int j = 0; j < 2; j++) {
                ull g0 = *reinterpret_cast<const ull*>(&Gre_s[(kc0 + j) * 200 + qof]);
                ADD2(acc_e[j], bo2, g0);
                acc_o[j] = 0ull;
            }
            #pragma unroll
            for (int uu = 1; uu <= 9; uu++) {
                const ulonglong2 e2 =
                    *reinterpret_cast<const ulonglong2*>(&e20p_s[p * 9 + uu - 1]);
                #pragma unroll
                for (int j = 0; j < 2; j++) {
                    int kc = kc0 + j;
                    ull gr = *reinterpret_cast<const ull*>(&Gre_s[kc * 200 + uu * 20 + qof]);
                    ull gi = *reinterpret_cast<const ull*>(&Gim_s[kc * 200 + uu * 20 + qof]);
                    if (uu & 1) {
                        FMA2(acc_o[j], e2.x, gr, acc_o[j]);
                        FMA2(acc_o[j], e2.y, gi, acc_o[j]);
                    } else {
                        FMA2(acc_e[j], e2.x, gr, acc_e[j]);
                        FMA2(acc_e[j], e2.y, gi, acc_e[j]);
                    }
                }
            }
            #pragma unroll
            for (int j = 0; j < 2; j++) {
                int kc = kc0 + j;
                ull s, d;
                ADD2(s, acc_e[j], acc_o[j]);
                ull no = acc_o[j] ^ SIGN2;
                ADD2(d, acc_e[j], no);
                *reinterpret_cast<ull*>(&outp[(k0 + kc) * 400 + p * 20 + qof]) = s;
                *reinterpret_cast<ull*>(&outp[(k0 + kc) * 400 + (p + 10) * 20 + qof]) = d;
            }
        }
        // S(c+1): reads Dbuf (filled during G-phase; barrier above orders it)
        if (c < 4) {
            S_PHASE()
        }
        __syncthreads();
    }
    #undef S_PHASE
    #undef D_LOAD
}

// ================= launch ====================================================
extern "C" void kernel_launch(void* const* d_in, const int* in_sizes, int n_in,
                              void* d_out, int out_size) {
    const float* x    = (const float*)d_in[0];  // (512, 2, 60, 60)
    const float* kern = (const float*)d_in[1];  // (2, 5, 6)
    const float* bias = (const float*)d_in[2];  // (5)
    float* out = (float*)d_out;                 // (512, 5, 20, 20, 20)

    h_build_tables();
    cudaMemcpyToSymbolAsync(TAB_d, host_tab, sizeof(float) * TAB_LEN, 0,
                            cudaMemcpyHostToDevice, 0);

    k_fhat<<<1024, 128>>>(x);
    dim3 g(512, 5);
    k_main<<<g, 256>>>(kern, bias, out);
}